// round 13
// baseline (speedup 1.0000x reference)
#include <cuda_runtime.h>
#include <cuda_fp16.h>
#include <cstdint>

#define S_TOK 8192
#define MDIM  1024
#define EDIM  8
#define HDIM  4096
#define CAP   1024

// ======================= helpers ===========================================
__device__ __forceinline__ uint32_t smem_u32(const void* p) {
    uint32_t a;
    asm("{ .reg .u64 t; cvta.to.shared.u64 t, %1; cvt.u32.u64 %0, t; }" : "=r"(a) : "l"(p));
    return a;
}
__device__ __forceinline__ void cp_async16(uint32_t dst, const void* src) {
    asm volatile("cp.async.cg.shared.global [%0], [%1], 16;" :: "r"(dst), "l"(src));
}
#define CP_COMMIT() asm volatile("cp.async.commit_group;" ::: "memory")
#define CP_WAIT(n)  asm volatile("cp.async.wait_group %0;" :: "n"(n) : "memory")

__device__ __forceinline__ void ldmatrix_x4(uint32_t* r, uint32_t addr) {
    asm volatile("ldmatrix.sync.aligned.m8n8.x4.shared.b16 {%0,%1,%2,%3}, [%4];"
                 : "=r"(r[0]), "=r"(r[1]), "=r"(r[2]), "=r"(r[3]) : "r"(addr));
}
__device__ __forceinline__ void mma_fp16(float* c, const uint32_t* a, uint32_t b0, uint32_t b1) {
    asm volatile("mma.sync.aligned.m16n8k16.row.col.f32.f16.f16.f32 "
                 "{%0,%1,%2,%3}, {%4,%5,%6,%7}, {%8,%9}, {%0,%1,%2,%3};"
                 : "+f"(c[0]), "+f"(c[1]), "+f"(c[2]), "+f"(c[3])
                 : "r"(a[0]), "r"(a[1]), "r"(a[2]), "r"(a[3]), "r"(b0), "r"(b1));
}

// ======================= scratch ===========================================
__device__ float g_gate[S_TOK];
__device__ int   g_exp[S_TOK];
__device__ int   g_loc[S_TOK];
__device__ int   g_slot2tok[S_TOK];
__device__ float g_sumgate[EDIM];
__device__ int   g_count[EDIM];
__device__ float g_laux;
__device__ __half g_disp[(size_t)EDIM * CAP * MDIM];
__device__ __half g_h[(size_t)S_TOK * HDIM];
__device__ __half g_w1t[(size_t)EDIM * HDIM * MDIM];
__device__ __half g_w2t[(size_t)EDIM * MDIM * HDIM];

// ======================= weight transpose + fp16 convert ===================
template <int K, int N>
__global__ __launch_bounds__(256) void wconv_kernel(const float* __restrict__ W,
                                                    __half* __restrict__ Wt) {
    __shared__ float tile[64][33];
    int e = blockIdx.z;
    const float* We = W + (size_t)e * K * N;
    __half* Wte = Wt + (size_t)e * N * K;
    int n0 = blockIdx.x * 32, k0 = blockIdx.y * 64;
    int tid = threadIdx.x;
#pragma unroll
    for (int i = tid; i < 64 * 32; i += 256) {
        int k = i >> 5, n = i & 31;
        tile[k][n] = We[(size_t)(k0 + k) * N + n0 + n];
    }
    __syncthreads();
#pragma unroll
    for (int i = tid; i < 32 * 32; i += 256) {
        int n = i >> 5, kp = i & 31;
        __half2 h = __floats2half2_rn(tile[2 * kp][n], tile[2 * kp + 1][n]);
        *(__half2*)(Wte + (size_t)(n0 + n) * K + k0 + 2 * kp) = h;
    }
}

// ======================= init ==============================================
__global__ void init_kernel() {
    int t = threadIdx.x;
    if (t < EDIM) { g_sumgate[t] = 0.f; g_count[t] = 0; }
}

// ======================= gating: 2 tokens/warp, float4 smem ================
__global__ __launch_bounds__(256) void gate_kernel(const float* __restrict__ x,
                                                   const float* __restrict__ wg) {
    __shared__ float swg[EDIM][MDIM];
    __shared__ float ssum[EDIM];
    __shared__ int   scnt[EDIM];
    int tid = threadIdx.x;
    for (int i = tid; i < MDIM * EDIM; i += 256)
        swg[i & 7][i >> 3] = wg[i];
    if (tid < EDIM) { ssum[tid] = 0.f; scnt[tid] = 0; }
    __syncthreads();

    int warp = tid >> 5, lane = tid & 31;
    int ta = blockIdx.x * 16 + warp * 2;
    const float4* xa = (const float4*)(x + (size_t)ta * MDIM);
    const float4* xb = (const float4*)(x + (size_t)(ta + 1) * MDIM);

    float accA[EDIM], accB[EDIM];
#pragma unroll
    for (int e = 0; e < EDIM; e++) { accA[e] = 0.f; accB[e] = 0.f; }

#pragma unroll 1
    for (int m4 = lane; m4 < MDIM / 4; m4 += 32) {
        float4 va = xa[m4];
        float4 vb = xb[m4];
#pragma unroll
        for (int e = 0; e < EDIM; e++) {
            float4 w = ((const float4*)swg[e])[m4];
            accA[e] = fmaf(va.x, w.x, fmaf(va.y, w.y, fmaf(va.z, w.z, fmaf(va.w, w.w, accA[e]))));
            accB[e] = fmaf(vb.x, w.x, fmaf(vb.y, w.y, fmaf(vb.z, w.z, fmaf(vb.w, w.w, accB[e]))));
        }
    }
#pragma unroll
    for (int e = 0; e < EDIM; e++)
#pragma unroll
        for (int o = 16; o > 0; o >>= 1) {
            accA[e] += __shfl_xor_sync(0xffffffffu, accA[e], o);
            accB[e] += __shfl_xor_sync(0xffffffffu, accB[e], o);
        }

    if (lane == 0) {
#pragma unroll 1
        for (int half = 0; half < 2; half++) {
            float* acc = half ? accB : accA;
            int t = ta + half;
            float mx = acc[0]; int bi = 0;
#pragma unroll
            for (int e = 1; e < EDIM; e++) if (acc[e] > mx) { mx = acc[e]; bi = e; }
            float g[EDIM], sum = 0.f;
#pragma unroll
            for (int e = 0; e < EDIM; e++) { g[e] = expf(acc[e] - mx); sum += g[e]; }
            float inv = 1.f / sum;
#pragma unroll
            for (int e = 0; e < EDIM; e++) { g[e] *= inv; atomicAdd(&ssum[e], g[e]); }
            atomicAdd(&scnt[bi], 1);
            g_exp[t]  = bi;
            g_gate[t] = g[bi];
        }
    }
    __syncthreads();
    if (tid < EDIM) {
        atomicAdd(&g_sumgate[tid], ssum[tid]);
        atomicAdd(&g_count[tid], scnt[tid]);
    }
}

// ======================= scan (parallel per-expert prefix) =================
__global__ __launch_bounds__(256) void scan_kernel() {
    __shared__ int sc[256][EDIM + 1];
    int tid = threadIdx.x;
    int warp = tid >> 5, lane = tid & 31;
    int t0 = tid * 32;
    int cnt[EDIM];
#pragma unroll
    for (int e = 0; e < EDIM; e++) cnt[e] = 0;
    for (int j = 0; j < 32; j++) cnt[g_exp[t0 + j]]++;
#pragma unroll
    for (int e = 0; e < EDIM; e++) sc[tid][e] = cnt[e];
    __syncthreads();
    if (warp < EDIM) {
        int e = warp;
        int v[8], run = 0;
#pragma unroll
        for (int j = 0; j < 8; j++) {
            int c = sc[lane * 8 + j][e];
            v[j] = run; run += c;
        }
        int pfx = run;
#pragma unroll
        for (int o = 1; o < 32; o <<= 1) {
            int n = __shfl_up_sync(0xffffffffu, pfx, o);
            if (lane >= o) pfx += n;
        }
        pfx -= run;
#pragma unroll
        for (int j = 0; j < 8; j++) sc[lane * 8 + j][e] = v[j] + pfx;
    }
    __syncthreads();
    int base[EDIM];
#pragma unroll
    for (int e = 0; e < EDIM; e++) base[e] = sc[tid][e];
    for (int j = 0; j < 32; j++) {
        int t = t0 + j;
        int e = g_exp[t];
        int loc = base[e]++;
        g_loc[t] = loc;
        if (loc >= CAP) g_gate[t] = 0.f;
        else            g_slot2tok[e * CAP + loc] = t;
    }
    if (tid == 0) {
        float l = 0.f;
        for (int e = 0; e < EDIM; e++)
            l += (g_sumgate[e] / (float)S_TOK) * ((float)g_count[e] / (float)S_TOK);
        g_laux = l * (float)EDIM;
    }
}

// ======================= scatter ===========================================
__global__ __launch_bounds__(256) void scatter_kernel(const float* __restrict__ x,
                                                      float* __restrict__ out, int out_size) {
    int tid = threadIdx.x;
    int t = blockIdx.x * 4 + (tid >> 6);
    int idx = tid & 63;
    float g = g_gate[t];
    if (g > 0.f) {
        int e = g_exp[t], loc = g_loc[t];
        const float4* src = (const float4*)(x + (size_t)t * MDIM);
        __half2* row = (__half2*)(g_disp + ((size_t)e * CAP + loc) * MDIM);
#pragma unroll
        for (int j = 0; j < 4; j++) {
            float4 v = src[idx + j * 64];
            row[(idx + j * 64) * 2]     = __floats2half2_rn(v.x, v.y);
            row[(idx + j * 64) * 2 + 1] = __floats2half2_rn(v.z, v.w);
        }
    } else {
        float4* orow = (float4*)(out + (size_t)t * MDIM);
#pragma unroll
        for (int j = 0; j < 4; j++) orow[idx + j * 64] = make_float4(0.f, 0.f, 0.f, 0.f);
    }
    if (t == 0 && tid == 0 && out_size > S_TOK * MDIM)
        out[(size_t)S_TOK * MDIM] = g_laux;
}

// ======================= fp16 mma GEMM, 3-stage pipeline ===================
static constexpr int GSMEM_BYTES = 3 * 32768 + 1024;

template <int K, int N, int EPI>
__global__ __launch_bounds__(256, 2) void mma_gemm(const __half* __restrict__ A,
                                                   const __half* __restrict__ B,
                                                   void* __restrict__ Cv,
                                                   int ytile0) {
    extern __shared__ char dynsmem[];
    char* sptr = (char*)((((uintptr_t)dynsmem) + 1023) & ~(uintptr_t)1023);
    uint32_t sbase = smem_u32(sptr);

    int tid = threadIdx.x;
    int wid = tid >> 5, lane = tid & 31;
    int row0 = (blockIdx.y + ytile0) * 128, col0 = blockIdx.x * 128;
    const __half* __restrict__ Be = B + (size_t)(row0 >> 10) * ((size_t)N * K);

    int lm = tid >> 1;
    int lh = tid & 1;
    const char* Ab = (const char*)(A + (size_t)(row0 + lm) * K);
    const char* Bb = (const char*)(Be + (size_t)(col0 + lm) * K);
    uint32_t swz = (uint32_t)(lm & 7);
    uint32_t dA = sbase + (uint32_t)lm * 128u;
    uint32_t dB = sbase + 16384u + (uint32_t)lm * 128u;

    auto load_tile = [&](int kt, int buf) {
        const char* As = Ab + kt * 128;
        const char* Bs = Bb + kt * 128;
        uint32_t off = (uint32_t)buf * 32768u;
#pragma unroll
        for (int c8 = 0; c8 < 4; c8++) {
            uint32_t lc = (uint32_t)(lh * 4 + c8);
            uint32_t p = (lc ^ swz) << 4;
            cp_async16(dA + off + p, As + lc * 16);
            cp_async16(dB + off + p, Bs + lc * 16);
        }
        CP_COMMIT();
    };

    int wm = (wid & 1) * 64;
    int wn = (wid >> 1) * 32;

    float acc[4][4][4];
#pragma unroll
    for (int i = 0; i < 4; i++)
#pragma unroll
        for (int j = 0; j < 4; j++)
#pragma unroll
            for (int q = 0; q < 4; q++) acc[i][j][q] = 0.f;

    constexpr int KT = K / 64;
    load_tile(0, 0);
    load_tile(1, 1);

    int rdbuf = 0, wrbuf = 2;
#pragma unroll 1
    for (int kt = 0; kt < KT; kt++) {
        if (kt + 2 < KT) { CP_WAIT(1); } else { CP_WAIT(0); }
        __syncthreads();
        if (kt + 2 < KT) load_tile(kt + 2, wrbuf);

        uint32_t sA = sbase + (uint32_t)rdbuf * 32768u;
        uint32_t sB = sA + 16384u;
#pragma unroll
        for (int kh = 0; kh < 2; kh++) {
            uint32_t bf[4][4];
#pragma unroll
            for (int jt = 0; jt < 4; jt++) {
                uint32_t row = (uint32_t)(wn + jt * 8 + (lane & 7));
                uint32_t c = (uint32_t)(lane >> 3) + (uint32_t)kh * 4u;
                ldmatrix_x4(bf[jt], sB + row * 128u + ((c ^ (row & 7u)) << 4));
            }
#pragma unroll
            for (int mi = 0; mi < 4; mi++) {
                uint32_t row = (uint32_t)(wm + mi * 16 + (lane & 15));
                uint32_t rbase = sA + row * 128u;
                uint32_t rsw = row & 7u;
#pragma unroll
                for (int s = 0; s < 2; s++) {
                    uint32_t c = (uint32_t)(kh * 4 + 2 * s + (lane >> 4));
                    uint32_t af[4];
                    ldmatrix_x4(af, rbase + ((c ^ rsw) << 4));
#pragma unroll
                    for (int jt = 0; jt < 4; jt++)
                        mma_fp16(acc[mi][jt], af, bf[jt][2 * s], bf[jt][2 * s + 1]);
                }
            }
        }
        rdbuf = (rdbuf == 2) ? 0 : rdbuf + 1;
        wrbuf = (wrbuf == 2) ? 0 : wrbuf + 1;
    }
    __syncthreads();

    if (EPI == 0) {
        __half* sh = (__half*)sptr;     // [128][132]
#pragma unroll
        for (int mi = 0; mi < 4; mi++) {
            int rl = wm + mi * 16 + (lane >> 2);
#pragma unroll
            for (int jt = 0; jt < 4; jt++) {
                int c = wn + jt * 8 + (lane & 3) * 2;
                *(__half2*)(sh + rl * 132 + c) =
                    __floats2half2_rn(fmaxf(acc[mi][jt][0], 0.f), fmaxf(acc[mi][jt][1], 0.f));
                *(__half2*)(sh + (rl + 8) * 132 + c) =
                    __floats2half2_rn(fmaxf(acc[mi][jt][2], 0.f), fmaxf(acc[mi][jt][3], 0.f));
            }
        }
        __syncthreads();
        __half* C = (__half*)Cv;
#pragma unroll
        for (int i = 0; i < 16; i++) {
            int rl = wid * 16 + i;
            uint2 v = *(uint2*)(sh + rl * 132 + lane * 4);
            *(uint2*)(C + (size_t)(row0 + rl) * N + col0 + lane * 4) = v;
        }
    } else {
        float* sf = (float*)sptr;       // [128][132]
#pragma unroll
        for (int mi = 0; mi < 4; mi++) {
            int rl = wm + mi * 16 + (lane >> 2);
#pragma unroll
            for (int jt = 0; jt < 4; jt++) {
                int c = wn + jt * 8 + (lane & 3) * 2;
                *(float2*)(sf + rl * 132 + c) = make_float2(acc[mi][jt][0], acc[mi][jt][1]);
                *(float2*)(sf + (rl + 8) * 132 + c) = make_float2(acc[mi][jt][2], acc[mi][jt][3]);
            }
        }
        __syncthreads();
        float* out = (float*)Cv;
#pragma unroll 1
        for (int i = 0; i < 16; i++) {
            int rl = wid * 16 + i;
            int slot = row0 + rl;
            int e = slot >> 10, loc = slot & (CAP - 1);
            if (loc < g_count[e]) {
                int tok = g_slot2tok[slot];
                float g = g_gate[tok];
                float4 v = *(float4*)(sf + rl * 132 + lane * 4);
                v.x *= g; v.y *= g; v.z *= g; v.w *= g;
                *(float4*)(out + (size_t)tok * MDIM + col0 + lane * 4) = v;
            }
        }
    }
}

// ======================= launch ============================================
extern "C" void kernel_launch(void* const* d_in, const int* in_sizes, int n_in,
                              void* d_out, int out_size) {
    const float* x  = (const float*)d_in[0];
    const float* wg = (const float*)d_in[1];
    const float* w1 = (const float*)d_in[2];
    const float* w2 = (const float*)d_in[3];
    float* out = (float*)d_out;

    __half *p_disp, *p_h, *p_w1t, *p_w2t;
    cudaGetSymbolAddress((void**)&p_disp, g_disp);
    cudaGetSymbolAddress((void**)&p_h,    g_h);
    cudaGetSymbolAddress((void**)&p_w1t,  g_w1t);
    cudaGetSymbolAddress((void**)&p_w2t,  g_w2t);

    // EXACT R11 resource footprint (passed the alloc guard): 3 streams, 8 events
    static cudaStream_t sW = nullptr, sA = nullptr, sB = nullptr;
    static cudaEvent_t evStart, evW1, evW2, evDisp, ev1a, ev1b, ev2a, ev2b;
    static bool init_done = false;
    if (!init_done) {
        cudaFuncSetAttribute(mma_gemm<MDIM, HDIM, 0>,
                             cudaFuncAttributeMaxDynamicSharedMemorySize, GSMEM_BYTES);
        cudaFuncSetAttribute(mma_gemm<HDIM, MDIM, 1>,
                             cudaFuncAttributeMaxDynamicSharedMemorySize, GSMEM_BYTES);
        cudaStreamCreateWithFlags(&sW, cudaStreamNonBlocking);
        cudaStreamCreateWithFlags(&sA, cudaStreamNonBlocking);
        cudaStreamCreateWithFlags(&sB, cudaStreamNonBlocking);
        cudaEventCreateWithFlags(&evStart, cudaEventDisableTiming);
        cudaEventCreateWithFlags(&evW1, cudaEventDisableTiming);
        cudaEventCreateWithFlags(&evW2, cudaEventDisableTiming);
        cudaEventCreateWithFlags(&evDisp, cudaEventDisableTiming);
        cudaEventCreateWithFlags(&ev1a, cudaEventDisableTiming);
        cudaEventCreateWithFlags(&ev1b, cudaEventDisableTiming);
        cudaEventCreateWithFlags(&ev2a, cudaEventDisableTiming);
        cudaEventCreateWithFlags(&ev2b, cudaEventDisableTiming);
        init_done = true;
    }

    // fork weight conversion
    cudaEventRecord(evStart, 0);
    cudaStreamWaitEvent(sW, evStart, 0);
    wconv_kernel<MDIM, HDIM><<<dim3(HDIM / 32, MDIM / 64, EDIM), 256, 0, sW>>>(w1, p_w1t);
    cudaEventRecord(evW1, sW);
    wconv_kernel<HDIM, MDIM><<<dim3(MDIM / 32, HDIM / 64, EDIM), 256, 0, sW>>>(w2, p_w2t);
    cudaEventRecord(evW2, sW);

    // token pipeline on main stream
    init_kernel<<<1, 32>>>();
    gate_kernel<<<S_TOK / 16, 256>>>(x, wg);
    scan_kernel<<<1, 256>>>();
    scatter_kernel<<<S_TOK / 4, 256>>>(x, out, out_size);
    cudaEventRecord(evDisp, 0);

    // 4 chunks on 2 streams: sA runs c0,c2; sB runs c1,c3 (G1ci -> G2ci each)
    constexpr int YT = 16;   // row-tiles per chunk (2 experts)
    cudaStream_t sC[2] = {sA, sB};
    for (int s = 0; s < 2; s++) {
        cudaStreamWaitEvent(sC[s], evDisp, 0);
        cudaStreamWaitEvent(sC[s], evW1, 0);
    }
    for (int i = 0; i < 4; i++) {
        cudaStream_t st = sC[i & 1];
        mma_gemm<MDIM, HDIM, 0><<<dim3(HDIM / 128, YT), 256, GSMEM_BYTES, st>>>(
            p_disp, p_w1t, p_h, i * YT);
        if (i < 2) cudaStreamWaitEvent(st, evW2, 0);   // first G2 on each stream needs w2t
        mma_gemm<HDIM, MDIM, 1><<<dim3(MDIM / 128, YT), 256, GSMEM_BYTES, st>>>(
            p_h, p_w2t, out, i * YT);
    }
    cudaEventRecord(ev2a, sA);
    cudaEventRecord(ev2b, sB);
    cudaStreamWaitEvent(0, ev2a, 0);
    cudaStreamWaitEvent(0, ev2b, 0);
}

// round 14
// speedup vs baseline: 1.0463x; 1.0463x over previous
#include <cuda_runtime.h>
#include <cuda_fp16.h>
#include <cstdint>

#define S_TOK 8192
#define MDIM  1024
#define EDIM  8
#define HDIM  4096
#define CAP   1024

// ======================= helpers ===========================================
__device__ __forceinline__ uint32_t smem_u32(const void* p) {
    uint32_t a;
    asm("{ .reg .u64 t; cvta.to.shared.u64 t, %1; cvt.u32.u64 %0, t; }" : "=r"(a) : "l"(p));
    return a;
}
__device__ __forceinline__ void cp_async16(uint32_t dst, const void* src) {
    asm volatile("cp.async.cg.shared.global [%0], [%1], 16;" :: "r"(dst), "l"(src));
}
#define CP_COMMIT() asm volatile("cp.async.commit_group;" ::: "memory")
#define CP_WAIT(n)  asm volatile("cp.async.wait_group %0;" :: "n"(n) : "memory")

__device__ __forceinline__ void ldmatrix_x4(uint32_t* r, uint32_t addr) {
    asm volatile("ldmatrix.sync.aligned.m8n8.x4.shared.b16 {%0,%1,%2,%3}, [%4];"
                 : "=r"(r[0]), "=r"(r[1]), "=r"(r[2]), "=r"(r[3]) : "r"(addr));
}
__device__ __forceinline__ void mma_fp16(float* c, const uint32_t* a, uint32_t b0, uint32_t b1) {
    asm volatile("mma.sync.aligned.m16n8k16.row.col.f32.f16.f16.f32 "
                 "{%0,%1,%2,%3}, {%4,%5,%6,%7}, {%8,%9}, {%0,%1,%2,%3};"
                 : "+f"(c[0]), "+f"(c[1]), "+f"(c[2]), "+f"(c[3])
                 : "r"(a[0]), "r"(a[1]), "r"(a[2]), "r"(a[3]), "r"(b0), "r"(b1));
}

// ======================= scratch ===========================================
__device__ float g_gate[S_TOK];
__device__ int   g_exp[S_TOK];
__device__ int   g_loc[S_TOK];
__device__ int   g_slot2tok[S_TOK];
__device__ float g_bsum[256 * EDIM];     // per-block softmax sums (gate -> scan)
__device__ int   g_count[EDIM];
__device__ float g_laux;
__device__ __half g_disp[(size_t)EDIM * CAP * MDIM];
__device__ __half g_h[(size_t)S_TOK * HDIM];
__device__ __half g_w1t[(size_t)EDIM * HDIM * MDIM];
__device__ __half g_w2t[(size_t)EDIM * MDIM * HDIM];

// ======================= weight transpose + fp16 convert ===================
template <int K, int N>
__global__ __launch_bounds__(256) void wconv_kernel(const float* __restrict__ W,
                                                    __half* __restrict__ Wt) {
    __shared__ float tile[64][33];
    int e = blockIdx.z;
    const float* We = W + (size_t)e * K * N;
    __half* Wte = Wt + (size_t)e * N * K;
    int n0 = blockIdx.x * 32, k0 = blockIdx.y * 64;
    int tid = threadIdx.x;
#pragma unroll
    for (int i = tid; i < 64 * 32; i += 256) {
        int k = i >> 5, n = i & 31;
        tile[k][n] = We[(size_t)(k0 + k) * N + n0 + n];
    }
    __syncthreads();
#pragma unroll
    for (int i = tid; i < 32 * 32; i += 256) {
        int n = i >> 5, kp = i & 31;
        __half2 h = __floats2half2_rn(tile[2 * kp][n], tile[2 * kp + 1][n]);
        *(__half2*)(Wte + (size_t)(n0 + n) * K + k0 + 2 * kp) = h;
    }
}

// ======================= gating: 4 tokens/warp, no global atomics ==========
// grid = S_TOK/32 = 256 blocks; block b writes g_bsum[b][e]
__global__ __launch_bounds__(256) void gate_kernel(const float* __restrict__ x,
                                                   const float* __restrict__ wg) {
    __shared__ float swg[EDIM][MDIM];
    __shared__ float ssum[EDIM];
    int tid = threadIdx.x;
    for (int i = tid; i < MDIM * EDIM; i += 256)
        swg[i & 7][i >> 3] = wg[i];
    if (tid < EDIM) ssum[tid] = 0.f;
    __syncthreads();

    int warp = tid >> 5, lane = tid & 31;
    int ta = blockIdx.x * 32 + warp * 4;
    const float4* xr0 = (const float4*)(x + (size_t)ta * MDIM);
    const float4* xr1 = (const float4*)(x + (size_t)(ta + 1) * MDIM);
    const float4* xr2 = (const float4*)(x + (size_t)(ta + 2) * MDIM);
    const float4* xr3 = (const float4*)(x + (size_t)(ta + 3) * MDIM);

    float acc[4][EDIM];
#pragma unroll
    for (int t = 0; t < 4; t++)
#pragma unroll
        for (int e = 0; e < EDIM; e++) acc[t][e] = 0.f;

#pragma unroll 1
    for (int m4 = lane; m4 < MDIM / 4; m4 += 32) {
        float4 v0 = xr0[m4];
        float4 v1 = xr1[m4];
        float4 v2 = xr2[m4];
        float4 v3 = xr3[m4];
#pragma unroll
        for (int e = 0; e < EDIM; e++) {
            float4 w = ((const float4*)swg[e])[m4];
            acc[0][e] = fmaf(v0.x, w.x, fmaf(v0.y, w.y, fmaf(v0.z, w.z, fmaf(v0.w, w.w, acc[0][e]))));
            acc[1][e] = fmaf(v1.x, w.x, fmaf(v1.y, w.y, fmaf(v1.z, w.z, fmaf(v1.w, w.w, acc[1][e]))));
            acc[2][e] = fmaf(v2.x, w.x, fmaf(v2.y, w.y, fmaf(v2.z, w.z, fmaf(v2.w, w.w, acc[2][e]))));
            acc[3][e] = fmaf(v3.x, w.x, fmaf(v3.y, w.y, fmaf(v3.z, w.z, fmaf(v3.w, w.w, acc[3][e]))));
        }
    }
#pragma unroll
    for (int t = 0; t < 4; t++)
#pragma unroll
        for (int e = 0; e < EDIM; e++)
#pragma unroll
            for (int o = 16; o > 0; o >>= 1)
                acc[t][e] += __shfl_xor_sync(0xffffffffu, acc[t][e], o);

    if (lane == 0) {
        float esum[EDIM];
#pragma unroll
        for (int e = 0; e < EDIM; e++) esum[e] = 0.f;
#pragma unroll 1
        for (int t = 0; t < 4; t++) {
            float* a = acc[t];
            float mx = a[0]; int bi = 0;
#pragma unroll
            for (int e = 1; e < EDIM; e++) if (a[e] > mx) { mx = a[e]; bi = e; }
            float g[EDIM], sum = 0.f;
#pragma unroll
            for (int e = 0; e < EDIM; e++) { g[e] = expf(a[e] - mx); sum += g[e]; }
            float inv = 1.f / sum;
#pragma unroll
            for (int e = 0; e < EDIM; e++) { g[e] *= inv; esum[e] += g[e]; }
            g_exp[ta + t]  = bi;
            g_gate[ta + t] = g[bi];
        }
#pragma unroll
        for (int e = 0; e < EDIM; e++) atomicAdd(&ssum[e], esum[e]);
    }
    __syncthreads();
    if (tid < EDIM) g_bsum[blockIdx.x * EDIM + tid] = ssum[tid];
}

// ======================= scan: prefix + counts + l_aux =====================
__global__ __launch_bounds__(256) void scan_kernel() {
    __shared__ int sc[256][EDIM + 1];
    __shared__ float s_sum[EDIM];
    __shared__ int   s_cnt[EDIM];
    int tid = threadIdx.x;
    int warp = tid >> 5, lane = tid & 31;
    int t0 = tid * 32;
    int cnt[EDIM];
#pragma unroll
    for (int e = 0; e < EDIM; e++) cnt[e] = 0;
    for (int j = 0; j < 32; j++) cnt[g_exp[t0 + j]]++;
#pragma unroll
    for (int e = 0; e < EDIM; e++) sc[tid][e] = cnt[e];
    __syncthreads();
    if (warp < EDIM) {
        int e = warp;
        int v[8], run = 0;
#pragma unroll
        for (int j = 0; j < 8; j++) {
            int c = sc[lane * 8 + j][e];
            v[j] = run; run += c;
        }
        int pfx = run;
#pragma unroll
        for (int o = 1; o < 32; o <<= 1) {
            int n = __shfl_up_sync(0xffffffffu, pfx, o);
            if (lane >= o) pfx += n;
        }
        int total = __shfl_sync(0xffffffffu, pfx, 31);
        pfx -= run;
#pragma unroll
        for (int j = 0; j < 8; j++) sc[lane * 8 + j][e] = v[j] + pfx;
        // reduce per-block softmax sums for expert e (256 blocks, 8 per lane)
        float s = 0.f;
#pragma unroll
        for (int j = 0; j < 8; j++) s += g_bsum[(lane * 8 + j) * EDIM + e];
#pragma unroll
        for (int o = 16; o > 0; o >>= 1) s += __shfl_xor_sync(0xffffffffu, s, o);
        if (lane == 0) {
            g_count[e] = (total < CAP) ? total : CAP;
            s_cnt[e] = total;
            s_sum[e] = s;
        }
    }
    __syncthreads();
    int base[EDIM];
#pragma unroll
    for (int e = 0; e < EDIM; e++) base[e] = sc[tid][e];
    for (int j = 0; j < 32; j++) {
        int t = t0 + j;
        int e = g_exp[t];
        int loc = base[e]++;
        g_loc[t] = loc;
        if (loc >= CAP) g_gate[t] = 0.f;
        else            g_slot2tok[e * CAP + loc] = t;
    }
    if (tid == 0) {
        float l = 0.f;
        for (int e = 0; e < EDIM; e++)
            l += (s_sum[e] / (float)S_TOK) * ((float)s_cnt[e] / (float)S_TOK);
        g_laux = l * (float)EDIM;
    }
}

// ======================= scatter ===========================================
__global__ __launch_bounds__(256) void scatter_kernel(const float* __restrict__ x,
                                                      float* __restrict__ out, int out_size) {
    int tid = threadIdx.x;
    int t = blockIdx.x * 4 + (tid >> 6);
    int idx = tid & 63;
    float g = g_gate[t];
    if (g > 0.f) {
        int e = g_exp[t], loc = g_loc[t];
        const float4* src = (const float4*)(x + (size_t)t * MDIM);
        __half2* row = (__half2*)(g_disp + ((size_t)e * CAP + loc) * MDIM);
#pragma unroll
        for (int j = 0; j < 4; j++) {
            float4 v = src[idx + j * 64];
            row[(idx + j * 64) * 2]     = __floats2half2_rn(v.x, v.y);
            row[(idx + j * 64) * 2 + 1] = __floats2half2_rn(v.z, v.w);
        }
    } else {
        float4* orow = (float4*)(out + (size_t)t * MDIM);
#pragma unroll
        for (int j = 0; j < 4; j++) orow[idx + j * 64] = make_float4(0.f, 0.f, 0.f, 0.f);
    }
    if (t == 0 && tid == 0 && out_size > S_TOK * MDIM)
        out[(size_t)S_TOK * MDIM] = g_laux;
}

// ======================= fp16 mma GEMM, 3-stage pipeline ===================
static constexpr int GSMEM_BYTES = 3 * 32768 + 1024;

template <int K, int N, int EPI>
__global__ __launch_bounds__(256, 2) void mma_gemm(const __half* __restrict__ A,
                                                   const __half* __restrict__ B,
                                                   void* __restrict__ Cv,
                                                   int ytile0) {
    extern __shared__ char dynsmem[];
    char* sptr = (char*)((((uintptr_t)dynsmem) + 1023) & ~(uintptr_t)1023);
    uint32_t sbase = smem_u32(sptr);

    int tid = threadIdx.x;
    int wid = tid >> 5, lane = tid & 31;
    int row0 = (blockIdx.y + ytile0) * 128, col0 = blockIdx.x * 128;
    const __half* __restrict__ Be = B + (size_t)(row0 >> 10) * ((size_t)N * K);

    int lm = tid >> 1;
    int lh = tid & 1;
    const char* Ab = (const char*)(A + (size_t)(row0 + lm) * K);
    const char* Bb = (const char*)(Be + (size_t)(col0 + lm) * K);
    uint32_t swz = (uint32_t)(lm & 7);
    uint32_t dA = sbase + (uint32_t)lm * 128u;
    uint32_t dB = sbase + 16384u + (uint32_t)lm * 128u;

    auto load_tile = [&](int kt, int buf) {
        const char* As = Ab + kt * 128;
        const char* Bs = Bb + kt * 128;
        uint32_t off = (uint32_t)buf * 32768u;
#pragma unroll
        for (int c8 = 0; c8 < 4; c8++) {
            uint32_t lc = (uint32_t)(lh * 4 + c8);
            uint32_t p = (lc ^ swz) << 4;
            cp_async16(dA + off + p, As + lc * 16);
            cp_async16(dB + off + p, Bs + lc * 16);
        }
        CP_COMMIT();
    };

    int wm = (wid & 1) * 64;
    int wn = (wid >> 1) * 32;

    float acc[4][4][4];
#pragma unroll
    for (int i = 0; i < 4; i++)
#pragma unroll
        for (int j = 0; j < 4; j++)
#pragma unroll
            for (int q = 0; q < 4; q++) acc[i][j][q] = 0.f;

    constexpr int KT = K / 64;
    load_tile(0, 0);
    load_tile(1, 1);

    int rdbuf = 0, wrbuf = 2;
#pragma unroll 1
    for (int kt = 0; kt < KT; kt++) {
        if (kt + 2 < KT) { CP_WAIT(1); } else { CP_WAIT(0); }
        __syncthreads();
        if (kt + 2 < KT) load_tile(kt + 2, wrbuf);

        uint32_t sA = sbase + (uint32_t)rdbuf * 32768u;
        uint32_t sB = sA + 16384u;
#pragma unroll
        for (int kh = 0; kh < 2; kh++) {
            uint32_t bf[4][4];
#pragma unroll
            for (int jt = 0; jt < 4; jt++) {
                uint32_t row = (uint32_t)(wn + jt * 8 + (lane & 7));
                uint32_t c = (uint32_t)(lane >> 3) + (uint32_t)kh * 4u;
                ldmatrix_x4(bf[jt], sB + row * 128u + ((c ^ (row & 7u)) << 4));
            }
#pragma unroll
            for (int mi = 0; mi < 4; mi++) {
                uint32_t row = (uint32_t)(wm + mi * 16 + (lane & 15));
                uint32_t rbase = sA + row * 128u;
                uint32_t rsw = row & 7u;
#pragma unroll
                for (int s = 0; s < 2; s++) {
                    uint32_t c = (uint32_t)(kh * 4 + 2 * s + (lane >> 4));
                    uint32_t af[4];
                    ldmatrix_x4(af, rbase + ((c ^ rsw) << 4));
#pragma unroll
                    for (int jt = 0; jt < 4; jt++)
                        mma_fp16(acc[mi][jt], af, bf[jt][2 * s], bf[jt][2 * s + 1]);
                }
            }
        }
        rdbuf = (rdbuf == 2) ? 0 : rdbuf + 1;
        wrbuf = (wrbuf == 2) ? 0 : wrbuf + 1;
    }
    __syncthreads();

    if (EPI == 0) {
        __half* sh = (__half*)sptr;     // [128][132]
#pragma unroll
        for (int mi = 0; mi < 4; mi++) {
            int rl = wm + mi * 16 + (lane >> 2);
#pragma unroll
            for (int jt = 0; jt < 4; jt++) {
                int c = wn + jt * 8 + (lane & 3) * 2;
                *(__half2*)(sh + rl * 132 + c) =
                    __floats2half2_rn(fmaxf(acc[mi][jt][0], 0.f), fmaxf(acc[mi][jt][1], 0.f));
                *(__half2*)(sh + (rl + 8) * 132 + c) =
                    __floats2half2_rn(fmaxf(acc[mi][jt][2], 0.f), fmaxf(acc[mi][jt][3], 0.f));
            }
        }
        __syncthreads();
        __half* C = (__half*)Cv;
#pragma unroll
        for (int i = 0; i < 16; i++) {
            int rl = wid * 16 + i;
            uint2 v = *(uint2*)(sh + rl * 132 + lane * 4);
            *(uint2*)(C + (size_t)(row0 + rl) * N + col0 + lane * 4) = v;
        }
    } else {
        float* sf = (float*)sptr;       // [128][132]
#pragma unroll
        for (int mi = 0; mi < 4; mi++) {
            int rl = wm + mi * 16 + (lane >> 2);
#pragma unroll
            for (int jt = 0; jt < 4; jt++) {
                int c = wn + jt * 8 + (lane & 3) * 2;
                *(float2*)(sf + rl * 132 + c) = make_float2(acc[mi][jt][0], acc[mi][jt][1]);
                *(float2*)(sf + (rl + 8) * 132 + c) = make_float2(acc[mi][jt][2], acc[mi][jt][3]);
            }
        }
        __syncthreads();
        float* out = (float*)Cv;
#pragma unroll 1
        for (int i = 0; i < 16; i++) {
            int rl = wid * 16 + i;
            int slot = row0 + rl;
            int e = slot >> 10, loc = slot & (CAP - 1);
            if (loc < g_count[e]) {
                int tok = g_slot2tok[slot];
                float g = g_gate[tok];
                float4 v = *(float4*)(sf + rl * 132 + lane * 4);
                v.x *= g; v.y *= g; v.z *= g; v.w *= g;
                *(float4*)(out + (size_t)tok * MDIM + col0 + lane * 4) = v;
            }
        }
    }
}

// ======================= launch (R11 schedule verbatim) ====================
extern "C" void kernel_launch(void* const* d_in, const int* in_sizes, int n_in,
                              void* d_out, int out_size) {
    const float* x  = (const float*)d_in[0];
    const float* wg = (const float*)d_in[1];
    const float* w1 = (const float*)d_in[2];
    const float* w2 = (const float*)d_in[3];
    float* out = (float*)d_out;

    __half *p_disp, *p_h, *p_w1t, *p_w2t;
    cudaGetSymbolAddress((void**)&p_disp, g_disp);
    cudaGetSymbolAddress((void**)&p_h,    g_h);
    cudaGetSymbolAddress((void**)&p_w1t,  g_w1t);
    cudaGetSymbolAddress((void**)&p_w2t,  g_w2t);

    static cudaStream_t sW = nullptr, sA = nullptr, sB = nullptr;
    static cudaEvent_t evStart, evW1, evW2, evDisp, ev1a, ev1b, ev2a, ev2b;
    static bool init_done = false;
    if (!init_done) {
        cudaFuncSetAttribute(mma_gemm<MDIM, HDIM, 0>,
                             cudaFuncAttributeMaxDynamicSharedMemorySize, GSMEM_BYTES);
        cudaFuncSetAttribute(mma_gemm<HDIM, MDIM, 1>,
                             cudaFuncAttributeMaxDynamicSharedMemorySize, GSMEM_BYTES);
        cudaStreamCreateWithFlags(&sW, cudaStreamNonBlocking);
        cudaStreamCreateWithFlags(&sA, cudaStreamNonBlocking);
        cudaStreamCreateWithFlags(&sB, cudaStreamNonBlocking);
        cudaEventCreateWithFlags(&evStart, cudaEventDisableTiming);
        cudaEventCreateWithFlags(&evW1, cudaEventDisableTiming);
        cudaEventCreateWithFlags(&evW2, cudaEventDisableTiming);
        cudaEventCreateWithFlags(&evDisp, cudaEventDisableTiming);
        cudaEventCreateWithFlags(&ev1a, cudaEventDisableTiming);
        cudaEventCreateWithFlags(&ev1b, cudaEventDisableTiming);
        cudaEventCreateWithFlags(&ev2a, cudaEventDisableTiming);
        cudaEventCreateWithFlags(&ev2b, cudaEventDisableTiming);
        init_done = true;
    }

    // fork weight conversion
    cudaEventRecord(evStart, 0);
    cudaStreamWaitEvent(sW, evStart, 0);
    wconv_kernel<MDIM, HDIM><<<dim3(HDIM / 32, MDIM / 64, EDIM), 256, 0, sW>>>(w1, p_w1t);
    cudaEventRecord(evW1, sW);
    wconv_kernel<HDIM, MDIM><<<dim3(MDIM / 32, HDIM / 64, EDIM), 256, 0, sW>>>(w2, p_w2t);
    cudaEventRecord(evW2, sW);

    // token pipeline on main stream (no init kernel needed)
    gate_kernel<<<S_TOK / 32, 256>>>(x, wg);
    scan_kernel<<<1, 256>>>();
    scatter_kernel<<<S_TOK / 4, 256>>>(x, out, out_size);
    cudaEventRecord(evDisp, 0);

    // expert-half chunked GEMMs (R11-proven): G1a||G1b, then G2a||G2b
    cudaStreamWaitEvent(sA, evDisp, 0);
    cudaStreamWaitEvent(sA, evW1, 0);
    mma_gemm<MDIM, HDIM, 0><<<dim3(HDIM / 128, 32), 256, GSMEM_BYTES, sA>>>(p_disp, p_w1t, p_h, 0);
    cudaEventRecord(ev1a, sA);

    cudaStreamWaitEvent(sB, evDisp, 0);
    cudaStreamWaitEvent(sB, evW1, 0);
    mma_gemm<MDIM, HDIM, 0><<<dim3(HDIM / 128, 32), 256, GSMEM_BYTES, sB>>>(p_disp, p_w1t, p_h, 32);
    cudaEventRecord(ev1b, sB);

    cudaStreamWaitEvent(sA, evW2, 0);
    mma_gemm<HDIM, MDIM, 1><<<dim3(MDIM / 128, 32), 256, GSMEM_BYTES, sA>>>(p_h, p_w2t, out, 0);
    cudaEventRecord(ev2a, sA);

    cudaStreamWaitEvent(sB, evW2, 0);
    mma_gemm<HDIM, MDIM, 1><<<dim3(MDIM / 128, 32), 256, GSMEM_BYTES, sB>>>(p_h, p_w2t, out, 32);
    cudaEventRecord(ev2b, sB);

    cudaStreamWaitEvent(0, ev2a, 0);
    cudaStreamWaitEvent(0, ev2b, 0);
}

// round 15
// speedup vs baseline: 1.0797x; 1.0320x over previous
#include <cuda_runtime.h>
#include <cuda_fp16.h>
#include <cstdint>

#define S_TOK 8192
#define MDIM  1024
#define EDIM  8
#define HDIM  4096
#define CAP   1024

// ======================= helpers ===========================================
__device__ __forceinline__ uint32_t smem_u32(const void* p) {
    uint32_t a;
    asm("{ .reg .u64 t; cvta.to.shared.u64 t, %1; cvt.u32.u64 %0, t; }" : "=r"(a) : "l"(p));
    return a;
}
__device__ __forceinline__ void cp_async16(uint32_t dst, const void* src) {
    asm volatile("cp.async.cg.shared.global [%0], [%1], 16;" :: "r"(dst), "l"(src));
}
#define CP_COMMIT() asm volatile("cp.async.commit_group;" ::: "memory")
#define CP_WAIT(n)  asm volatile("cp.async.wait_group %0;" :: "n"(n) : "memory")

__device__ __forceinline__ void ldmatrix_x4(uint32_t* r, uint32_t addr) {
    asm volatile("ldmatrix.sync.aligned.m8n8.x4.shared.b16 {%0,%1,%2,%3}, [%4];"
                 : "=r"(r[0]), "=r"(r[1]), "=r"(r[2]), "=r"(r[3]) : "r"(addr));
}
__device__ __forceinline__ void mma_fp16(float* c, const uint32_t* a, uint32_t b0, uint32_t b1) {
    asm volatile("mma.sync.aligned.m16n8k16.row.col.f32.f16.f16.f32 "
                 "{%0,%1,%2,%3}, {%4,%5,%6,%7}, {%8,%9}, {%0,%1,%2,%3};"
                 : "+f"(c[0]), "+f"(c[1]), "+f"(c[2]), "+f"(c[3])
                 : "r"(a[0]), "r"(a[1]), "r"(a[2]), "r"(a[3]), "r"(b0), "r"(b1));
}

// ======================= scratch ===========================================
__device__ float g_gate[S_TOK];
__device__ int   g_exp[S_TOK];
__device__ int   g_slot2tok[S_TOK];
__device__ float g_bsum[256 * EDIM];     // per-chunk softmax sums
__device__ int   g_bcnt[256 * EDIM];     // per-chunk expert counts
__device__ int   g_cbase[256 * EDIM];    // per-chunk expert base offsets
__device__ int   g_count[EDIM];
__device__ float g_laux;
__device__ __half g_disp[(size_t)EDIM * CAP * MDIM];
__device__ __half g_h[(size_t)S_TOK * HDIM];
__device__ __half g_w1t[(size_t)EDIM * HDIM * MDIM];
__device__ __half g_w2t[(size_t)EDIM * MDIM * HDIM];

// ======================= weight transpose + fp16 convert ===================
template <int K, int N>
__global__ __launch_bounds__(256) void wconv_kernel(const float* __restrict__ W,
                                                    __half* __restrict__ Wt) {
    __shared__ float tile[64][33];
    int e = blockIdx.z;
    const float* We = W + (size_t)e * K * N;
    __half* Wte = Wt + (size_t)e * N * K;
    int n0 = blockIdx.x * 32, k0 = blockIdx.y * 64;
    int tid = threadIdx.x;
#pragma unroll
    for (int i = tid; i < 64 * 32; i += 256) {
        int k = i >> 5, n = i & 31;
        tile[k][n] = We[(size_t)(k0 + k) * N + n0 + n];
    }
    __syncthreads();
#pragma unroll
    for (int i = tid; i < 32 * 32; i += 256) {
        int n = i >> 5, kp = i & 31;
        __half2 h = __floats2half2_rn(tile[2 * kp][n], tile[2 * kp + 1][n]);
        *(__half2*)(Wte + (size_t)(n0 + n) * K + k0 + 2 * kp) = h;
    }
}

// ======================= gating: 4 tokens/warp + chunk counts ==============
// grid = 256 blocks x 32 tokens; writes g_exp/g_gate + g_bsum/g_bcnt per chunk
__global__ __launch_bounds__(256) void gate_kernel(const float* __restrict__ x,
                                                   const float* __restrict__ wg) {
    __shared__ float swg[EDIM][MDIM];
    __shared__ float ssum[EDIM];
    __shared__ int   scnt[EDIM];
    int tid = threadIdx.x;
    for (int i = tid; i < MDIM * EDIM; i += 256)
        swg[i & 7][i >> 3] = wg[i];
    if (tid < EDIM) { ssum[tid] = 0.f; scnt[tid] = 0; }
    __syncthreads();

    int warp = tid >> 5, lane = tid & 31;
    int ta = blockIdx.x * 32 + warp * 4;
    const float4* xr0 = (const float4*)(x + (size_t)ta * MDIM);
    const float4* xr1 = (const float4*)(x + (size_t)(ta + 1) * MDIM);
    const float4* xr2 = (const float4*)(x + (size_t)(ta + 2) * MDIM);
    const float4* xr3 = (const float4*)(x + (size_t)(ta + 3) * MDIM);

    float acc[4][EDIM];
#pragma unroll
    for (int t = 0; t < 4; t++)
#pragma unroll
        for (int e = 0; e < EDIM; e++) acc[t][e] = 0.f;

#pragma unroll 1
    for (int m4 = lane; m4 < MDIM / 4; m4 += 32) {
        float4 v0 = xr0[m4];
        float4 v1 = xr1[m4];
        float4 v2 = xr2[m4];
        float4 v3 = xr3[m4];
#pragma unroll
        for (int e = 0; e < EDIM; e++) {
            float4 w = ((const float4*)swg[e])[m4];
            acc[0][e] = fmaf(v0.x, w.x, fmaf(v0.y, w.y, fmaf(v0.z, w.z, fmaf(v0.w, w.w, acc[0][e]))));
            acc[1][e] = fmaf(v1.x, w.x, fmaf(v1.y, w.y, fmaf(v1.z, w.z, fmaf(v1.w, w.w, acc[1][e]))));
            acc[2][e] = fmaf(v2.x, w.x, fmaf(v2.y, w.y, fmaf(v2.z, w.z, fmaf(v2.w, w.w, acc[2][e]))));
            acc[3][e] = fmaf(v3.x, w.x, fmaf(v3.y, w.y, fmaf(v3.z, w.z, fmaf(v3.w, w.w, acc[3][e]))));
        }
    }
#pragma unroll
    for (int t = 0; t < 4; t++)
#pragma unroll
        for (int e = 0; e < EDIM; e++)
#pragma unroll
            for (int o = 16; o > 0; o >>= 1)
                acc[t][e] += __shfl_xor_sync(0xffffffffu, acc[t][e], o);

    if (lane == 0) {
        float esum[EDIM];
#pragma unroll
        for (int e = 0; e < EDIM; e++) esum[e] = 0.f;
#pragma unroll 1
        for (int t = 0; t < 4; t++) {
            float* a = acc[t];
            float mx = a[0]; int bi = 0;
#pragma unroll
            for (int e = 1; e < EDIM; e++) if (a[e] > mx) { mx = a[e]; bi = e; }
            float g[EDIM], sum = 0.f;
#pragma unroll
            for (int e = 0; e < EDIM; e++) { g[e] = expf(a[e] - mx); sum += g[e]; }
            float inv = 1.f / sum;
#pragma unroll
            for (int e = 0; e < EDIM; e++) { g[e] *= inv; esum[e] += g[e]; }
            g_exp[ta + t]  = bi;
            g_gate[ta + t] = g[bi];
            atomicAdd(&scnt[bi], 1);
        }
#pragma unroll
        for (int e = 0; e < EDIM; e++) atomicAdd(&ssum[e], esum[e]);
    }
    __syncthreads();
    if (tid < EDIM) {
        g_bsum[blockIdx.x * EDIM + tid] = ssum[tid];
        g_bcnt[blockIdx.x * EDIM + tid] = scnt[tid];
    }
}

// ======================= scan: chunk-level prefix only =====================
__global__ __launch_bounds__(256) void scan_kernel() {
    __shared__ float s_sum[EDIM];
    __shared__ int   s_cnt[EDIM];
    int tid = threadIdx.x;
    int warp = tid >> 5, lane = tid & 31;
    // warp e: exclusive prefix of g_bcnt[.][e] over 256 chunks (8 per lane)
    {
        int e = warp;
        int v[8], run = 0;
#pragma unroll
        for (int j = 0; j < 8; j++) {
            int c = g_bcnt[(lane * 8 + j) * EDIM + e];
            v[j] = run; run += c;
        }
        int pfx = run;
#pragma unroll
        for (int o = 1; o < 32; o <<= 1) {
            int n = __shfl_up_sync(0xffffffffu, pfx, o);
            if (lane >= o) pfx += n;
        }
        int total = __shfl_sync(0xffffffffu, pfx, 31);
        pfx -= run;
#pragma unroll
        for (int j = 0; j < 8; j++) g_cbase[(lane * 8 + j) * EDIM + e] = v[j] + pfx;
        float s = 0.f;
#pragma unroll
        for (int j = 0; j < 8; j++) s += g_bsum[(lane * 8 + j) * EDIM + e];
#pragma unroll
        for (int o = 16; o > 0; o >>= 1) s += __shfl_xor_sync(0xffffffffu, s, o);
        if (lane == 0) {
            g_count[e] = (total < CAP) ? total : CAP;
            s_cnt[e] = total;
            s_sum[e] = s;
        }
    }
    __syncthreads();
    if (tid == 0) {
        float l = 0.f;
        for (int e = 0; e < EDIM; e++)
            l += (s_sum[e] / (float)S_TOK) * ((float)s_cnt[e] / (float)S_TOK);
        g_laux = l * (float)EDIM;
    }
}

// ======================= scatter: parallel rank + copy =====================
// grid = 256 blocks x 32 tokens; warp 0 computes loc via match_any rank
__global__ __launch_bounds__(256) void scatter_kernel(const float* __restrict__ x,
                                                      float* __restrict__ out, int out_size) {
    __shared__ int se[32], sloc[32];
    int tid = threadIdx.x;
    int b = blockIdx.x;
    if (tid < 32) {
        int t = b * 32 + tid;
        int e = g_exp[t];
        unsigned mask = __match_any_sync(0xffffffffu, e);
        int rank = __popc(mask & ((1u << tid) - 1u));
        int loc = g_cbase[b * EDIM + e] + rank;
        bool kept = loc < CAP;
        se[tid] = e;
        sloc[tid] = kept ? loc : -1;
        if (kept) g_slot2tok[e * CAP + loc] = t;
    }
    __syncthreads();
    int wid = tid >> 5, lane = tid & 31;
#pragma unroll 1
    for (int j = 0; j < 4; j++) {
        int tt = wid * 4 + j;
        int t = b * 32 + tt;
        int loc = sloc[tt];
        if (loc >= 0) {
            const float4* src = (const float4*)(x + (size_t)t * MDIM);
            __half2* row = (__half2*)(g_disp + ((size_t)se[tt] * CAP + loc) * MDIM);
#pragma unroll
            for (int k = 0; k < 8; k++) {
                float4 v = src[lane + k * 32];
                row[(lane + k * 32) * 2]     = __floats2half2_rn(v.x, v.y);
                row[(lane + k * 32) * 2 + 1] = __floats2half2_rn(v.z, v.w);
            }
        } else {
            float4* orow = (float4*)(out + (size_t)t * MDIM);
#pragma unroll
            for (int k = 0; k < 8; k++) orow[lane + k * 32] = make_float4(0.f, 0.f, 0.f, 0.f);
        }
    }
    if (b == 0 && tid == 0 && out_size > S_TOK * MDIM)
        out[(size_t)S_TOK * MDIM] = g_laux;
}

// ======================= fp16 mma GEMM, 3-stage pipeline ===================
static constexpr int GSMEM_BYTES = 3 * 32768 + 1024;

template <int K, int N, int EPI>
__global__ __launch_bounds__(256, 2) void mma_gemm(const __half* __restrict__ A,
                                                   const __half* __restrict__ B,
                                                   void* __restrict__ Cv,
                                                   int ytile0) {
    extern __shared__ char dynsmem[];
    char* sptr = (char*)((((uintptr_t)dynsmem) + 1023) & ~(uintptr_t)1023);
    uint32_t sbase = smem_u32(sptr);

    int tid = threadIdx.x;
    int wid = tid >> 5, lane = tid & 31;
    int row0 = (blockIdx.y + ytile0) * 128, col0 = blockIdx.x * 128;
    const __half* __restrict__ Be = B + (size_t)(row0 >> 10) * ((size_t)N * K);

    int lm = tid >> 1;
    int lh = tid & 1;
    const char* Ab = (const char*)(A + (size_t)(row0 + lm) * K);
    const char* Bb = (const char*)(Be + (size_t)(col0 + lm) * K);
    uint32_t swz = (uint32_t)(lm & 7);
    uint32_t dA = sbase + (uint32_t)lm * 128u;
    uint32_t dB = sbase + 16384u + (uint32_t)lm * 128u;

    auto load_tile = [&](int kt, int buf) {
        const char* As = Ab + kt * 128;
        const char* Bs = Bb + kt * 128;
        uint32_t off = (uint32_t)buf * 32768u;
#pragma unroll
        for (int c8 = 0; c8 < 4; c8++) {
            uint32_t lc = (uint32_t)(lh * 4 + c8);
            uint32_t p = (lc ^ swz) << 4;
            cp_async16(dA + off + p, As + lc * 16);
            cp_async16(dB + off + p, Bs + lc * 16);
        }
        CP_COMMIT();
    };

    int wm = (wid & 1) * 64;
    int wn = (wid >> 1) * 32;

    float acc[4][4][4];
#pragma unroll
    for (int i = 0; i < 4; i++)
#pragma unroll
        for (int j = 0; j < 4; j++)
#pragma unroll
            for (int q = 0; q < 4; q++) acc[i][j][q] = 0.f;

    constexpr int KT = K / 64;
    load_tile(0, 0);
    load_tile(1, 1);

    int rdbuf = 0, wrbuf = 2;
#pragma unroll 1
    for (int kt = 0; kt < KT; kt++) {
        if (kt + 2 < KT) { CP_WAIT(1); } else { CP_WAIT(0); }
        __syncthreads();
        if (kt + 2 < KT) load_tile(kt + 2, wrbuf);

        uint32_t sA = sbase + (uint32_t)rdbuf * 32768u;
        uint32_t sB = sA + 16384u;
#pragma unroll
        for (int kh = 0; kh < 2; kh++) {
            uint32_t bf[4][4];
#pragma unroll
            for (int jt = 0; jt < 4; jt++) {
                uint32_t row = (uint32_t)(wn + jt * 8 + (lane & 7));
                uint32_t c = (uint32_t)(lane >> 3) + (uint32_t)kh * 4u;
                ldmatrix_x4(bf[jt], sB + row * 128u + ((c ^ (row & 7u)) << 4));
            }
#pragma unroll
            for (int mi = 0; mi < 4; mi++) {
                uint32_t row = (uint32_t)(wm + mi * 16 + (lane & 15));
                uint32_t rbase = sA + row * 128u;
                uint32_t rsw = row & 7u;
#pragma unroll
                for (int s = 0; s < 2; s++) {
                    uint32_t c = (uint32_t)(kh * 4 + 2 * s + (lane >> 4));
                    uint32_t af[4];
                    ldmatrix_x4(af, rbase + ((c ^ rsw) << 4));
#pragma unroll
                    for (int jt = 0; jt < 4; jt++)
                        mma_fp16(acc[mi][jt], af, bf[jt][2 * s], bf[jt][2 * s + 1]);
                }
            }
        }
        rdbuf = (rdbuf == 2) ? 0 : rdbuf + 1;
        wrbuf = (wrbuf == 2) ? 0 : wrbuf + 1;
    }
    __syncthreads();

    if (EPI == 0) {
        __half* sh = (__half*)sptr;     // [128][132]
#pragma unroll
        for (int mi = 0; mi < 4; mi++) {
            int rl = wm + mi * 16 + (lane >> 2);
#pragma unroll
            for (int jt = 0; jt < 4; jt++) {
                int c = wn + jt * 8 + (lane & 3) * 2;
                *(__half2*)(sh + rl * 132 + c) =
                    __floats2half2_rn(fmaxf(acc[mi][jt][0], 0.f), fmaxf(acc[mi][jt][1], 0.f));
                *(__half2*)(sh + (rl + 8) * 132 + c) =
                    __floats2half2_rn(fmaxf(acc[mi][jt][2], 0.f), fmaxf(acc[mi][jt][3], 0.f));
            }
        }
        __syncthreads();
        __half* C = (__half*)Cv;
#pragma unroll
        for (int i = 0; i < 16; i++) {
            int rl = wid * 16 + i;
            uint2 v = *(uint2*)(sh + rl * 132 + lane * 4);
            *(uint2*)(C + (size_t)(row0 + rl) * N + col0 + lane * 4) = v;
        }
    } else {
        float* sf = (float*)sptr;       // [128][132]
#pragma unroll
        for (int mi = 0; mi < 4; mi++) {
            int rl = wm + mi * 16 + (lane >> 2);
#pragma unroll
            for (int jt = 0; jt < 4; jt++) {
                int c = wn + jt * 8 + (lane & 3) * 2;
                *(float2*)(sf + rl * 132 + c) = make_float2(acc[mi][jt][0], acc[mi][jt][1]);
                *(float2*)(sf + (rl + 8) * 132 + c) = make_float2(acc[mi][jt][2], acc[mi][jt][3]);
            }
        }
        __syncthreads();
        float* out = (float*)Cv;
#pragma unroll 1
        for (int i = 0; i < 16; i++) {
            int rl = wid * 16 + i;
            int slot = row0 + rl;
            int e = slot >> 10, loc = slot & (CAP - 1);
            if (loc < g_count[e]) {
                int tok = g_slot2tok[slot];
                float g = g_gate[tok];
                float4 v = *(float4*)(sf + rl * 132 + lane * 4);
                v.x *= g; v.y *= g; v.z *= g; v.w *= g;
                *(float4*)(out + (size_t)tok * MDIM + col0 + lane * 4) = v;
            }
        }
    }
}

// ======================= launch (R11 schedule) =============================
extern "C" void kernel_launch(void* const* d_in, const int* in_sizes, int n_in,
                              void* d_out, int out_size) {
    const float* x  = (const float*)d_in[0];
    const float* wg = (const float*)d_in[1];
    const float* w1 = (const float*)d_in[2];
    const float* w2 = (const float*)d_in[3];
    float* out = (float*)d_out;

    __half *p_disp, *p_h, *p_w1t, *p_w2t;
    cudaGetSymbolAddress((void**)&p_disp, g_disp);
    cudaGetSymbolAddress((void**)&p_h,    g_h);
    cudaGetSymbolAddress((void**)&p_w1t,  g_w1t);
    cudaGetSymbolAddress((void**)&p_w2t,  g_w2t);

    static cudaStream_t sW = nullptr, sA = nullptr, sB = nullptr;
    static cudaEvent_t evStart, evW1, evW2, evDisp, ev1a, ev1b, ev2a, ev2b;
    static bool init_done = false;
    if (!init_done) {
        cudaFuncSetAttribute(mma_gemm<MDIM, HDIM, 0>,
                             cudaFuncAttributeMaxDynamicSharedMemorySize, GSMEM_BYTES);
        cudaFuncSetAttribute(mma_gemm<HDIM, MDIM, 1>,
                             cudaFuncAttributeMaxDynamicSharedMemorySize, GSMEM_BYTES);
        cudaStreamCreateWithFlags(&sW, cudaStreamNonBlocking);
        cudaStreamCreateWithFlags(&sA, cudaStreamNonBlocking);
        cudaStreamCreateWithFlags(&sB, cudaStreamNonBlocking);
        cudaEventCreateWithFlags(&evStart, cudaEventDisableTiming);
        cudaEventCreateWithFlags(&evW1, cudaEventDisableTiming);
        cudaEventCreateWithFlags(&evW2, cudaEventDisableTiming);
        cudaEventCreateWithFlags(&evDisp, cudaEventDisableTiming);
        cudaEventCreateWithFlags(&ev1a, cudaEventDisableTiming);
        cudaEventCreateWithFlags(&ev1b, cudaEventDisableTiming);
        cudaEventCreateWithFlags(&ev2a, cudaEventDisableTiming);
        cudaEventCreateWithFlags(&ev2b, cudaEventDisableTiming);
        init_done = true;
    }

    // fork weight conversion
    cudaEventRecord(evStart, 0);
    cudaStreamWaitEvent(sW, evStart, 0);
    wconv_kernel<MDIM, HDIM><<<dim3(HDIM / 32, MDIM / 64, EDIM), 256, 0, sW>>>(w1, p_w1t);
    cudaEventRecord(evW1, sW);
    wconv_kernel<HDIM, MDIM><<<dim3(MDIM / 32, HDIM / 64, EDIM), 256, 0, sW>>>(w2, p_w2t);
    cudaEventRecord(evW2, sW);

    // token pipeline on main stream
    gate_kernel<<<S_TOK / 32, 256>>>(x, wg);
    scan_kernel<<<1, 256>>>();
    scatter_kernel<<<S_TOK / 32, 256>>>(x, out, out_size);
    cudaEventRecord(evDisp, 0);

    // expert-half chunked GEMMs (R11-proven)
    cudaStreamWaitEvent(sA, evDisp, 0);
    cudaStreamWaitEvent(sA, evW1, 0);
    mma_gemm<MDIM, HDIM, 0><<<dim3(HDIM / 128, 32), 256, GSMEM_BYTES, sA>>>(p_disp, p_w1t, p_h, 0);
    cudaEventRecord(ev1a, sA);

    cudaStreamWaitEvent(sB, evDisp, 0);
    cudaStreamWaitEvent(sB, evW1, 0);
    mma_gemm<MDIM, HDIM, 0><<<dim3(HDIM / 128, 32), 256, GSMEM_BYTES, sB>>>(p_disp, p_w1t, p_h, 32);
    cudaEventRecord(ev1b, sB);

    cudaStreamWaitEvent(sA, evW2, 0);
    mma_gemm<HDIM, MDIM, 1><<<dim3(MDIM / 128, 32), 256, GSMEM_BYTES, sA>>>(p_h, p_w2t, out, 0);
    cudaEventRecord(ev2a, sA);

    cudaStreamWaitEvent(sB, evW2, 0);
    mma_gemm<HDIM, MDIM, 1><<<dim3(MDIM / 128, 32), 256, GSMEM_BYTES, sB>>>(p_h, p_w2t, out, 32);
    cudaEventRecord(ev2b, sB);

    cudaStreamWaitEvent(0, ev2a, 0);
    cudaStreamWaitEvent(0, ev2b, 0);
}

// round 16
// speedup vs baseline: 1.0889x; 1.0085x over previous
#include <cuda_runtime.h>
#include <cuda_fp16.h>
#include <cstdint>

#define S_TOK 8192
#define MDIM  1024
#define EDIM  8
#define HDIM  4096
#define CAP   1024

// ======================= helpers ===========================================
__device__ __forceinline__ uint32_t smem_u32(const void* p) {
    uint32_t a;
    asm("{ .reg .u64 t; cvta.to.shared.u64 t, %1; cvt.u32.u64 %0, t; }" : "=r"(a) : "l"(p));
    return a;
}
__device__ __forceinline__ void cp_async16(uint32_t dst, const void* src) {
    asm volatile("cp.async.cg.shared.global [%0], [%1], 16;" :: "r"(dst), "l"(src));
}
#define CP_COMMIT() asm volatile("cp.async.commit_group;" ::: "memory")
#define CP_WAIT(n)  asm volatile("cp.async.wait_group %0;" :: "n"(n) : "memory")

__device__ __forceinline__ void ldmatrix_x4(uint32_t* r, uint32_t addr) {
    asm volatile("ldmatrix.sync.aligned.m8n8.x4.shared.b16 {%0,%1,%2,%3}, [%4];"
                 : "=r"(r[0]), "=r"(r[1]), "=r"(r[2]), "=r"(r[3]) : "r"(addr));
}
__device__ __forceinline__ void mma_fp16(float* c, const uint32_t* a, uint32_t b0, uint32_t b1) {
    asm volatile("mma.sync.aligned.m16n8k16.row.col.f32.f16.f16.f32 "
                 "{%0,%1,%2,%3}, {%4,%5,%6,%7}, {%8,%9}, {%0,%1,%2,%3};"
                 : "+f"(c[0]), "+f"(c[1]), "+f"(c[2]), "+f"(c[3])
                 : "r"(a[0]), "r"(a[1]), "r"(a[2]), "r"(a[3]), "r"(b0), "r"(b1));
}

// ======================= scratch ===========================================
__device__ float g_gate[S_TOK];
__device__ int   g_exp[S_TOK];
__device__ int   g_slot2tok[S_TOK];
__device__ float g_bsum[256 * EDIM];     // per-chunk softmax sums
__device__ int   g_bcnt[256 * EDIM];     // per-chunk expert counts
__device__ int   g_count[EDIM];
__device__ __half g_disp[(size_t)EDIM * CAP * MDIM];
__device__ __half g_h[(size_t)S_TOK * HDIM];
__device__ __half g_w1t[(size_t)EDIM * HDIM * MDIM];
__device__ __half g_w2t[(size_t)EDIM * MDIM * HDIM];

// ======================= weight transpose + fp16 convert ===================
template <int K, int N>
__global__ __launch_bounds__(256) void wconv_kernel(const float* __restrict__ W,
                                                    __half* __restrict__ Wt) {
    __shared__ float tile[64][33];
    int e = blockIdx.z;
    const float* We = W + (size_t)e * K * N;
    __half* Wte = Wt + (size_t)e * N * K;
    int n0 = blockIdx.x * 32, k0 = blockIdx.y * 64;
    int tid = threadIdx.x;
#pragma unroll
    for (int i = tid; i < 64 * 32; i += 256) {
        int k = i >> 5, n = i & 31;
        tile[k][n] = We[(size_t)(k0 + k) * N + n0 + n];
    }
    __syncthreads();
#pragma unroll
    for (int i = tid; i < 32 * 32; i += 256) {
        int n = i >> 5, kp = i & 31;
        __half2 h = __floats2half2_rn(tile[2 * kp][n], tile[2 * kp + 1][n]);
        *(__half2*)(Wte + (size_t)(n0 + n) * K + k0 + 2 * kp) = h;
    }
}

// ======================= gating: 4 tokens/warp + chunk counts ==============
__global__ __launch_bounds__(256) void gate_kernel(const float* __restrict__ x,
                                                   const float* __restrict__ wg) {
    __shared__ float swg[EDIM][MDIM];
    __shared__ float ssum[EDIM];
    __shared__ int   scnt[EDIM];
    int tid = threadIdx.x;
    for (int i = tid; i < MDIM * EDIM; i += 256)
        swg[i & 7][i >> 3] = wg[i];
    if (tid < EDIM) { ssum[tid] = 0.f; scnt[tid] = 0; }
    __syncthreads();

    int warp = tid >> 5, lane = tid & 31;
    int ta = blockIdx.x * 32 + warp * 4;
    const float4* xr0 = (const float4*)(x + (size_t)ta * MDIM);
    const float4* xr1 = (const float4*)(x + (size_t)(ta + 1) * MDIM);
    const float4* xr2 = (const float4*)(x + (size_t)(ta + 2) * MDIM);
    const float4* xr3 = (const float4*)(x + (size_t)(ta + 3) * MDIM);

    float acc[4][EDIM];
#pragma unroll
    for (int t = 0; t < 4; t++)
#pragma unroll
        for (int e = 0; e < EDIM; e++) acc[t][e] = 0.f;

#pragma unroll 1
    for (int m4 = lane; m4 < MDIM / 4; m4 += 32) {
        float4 v0 = xr0[m4];
        float4 v1 = xr1[m4];
        float4 v2 = xr2[m4];
        float4 v3 = xr3[m4];
#pragma unroll
        for (int e = 0; e < EDIM; e++) {
            float4 w = ((const float4*)swg[e])[m4];
            acc[0][e] = fmaf(v0.x, w.x, fmaf(v0.y, w.y, fmaf(v0.z, w.z, fmaf(v0.w, w.w, acc[0][e]))));
            acc[1][e] = fmaf(v1.x, w.x, fmaf(v1.y, w.y, fmaf(v1.z, w.z, fmaf(v1.w, w.w, acc[1][e]))));
            acc[2][e] = fmaf(v2.x, w.x, fmaf(v2.y, w.y, fmaf(v2.z, w.z, fmaf(v2.w, w.w, acc[2][e]))));
            acc[3][e] = fmaf(v3.x, w.x, fmaf(v3.y, w.y, fmaf(v3.z, w.z, fmaf(v3.w, w.w, acc[3][e]))));
        }
    }
#pragma unroll
    for (int t = 0; t < 4; t++)
#pragma unroll
        for (int e = 0; e < EDIM; e++)
#pragma unroll
            for (int o = 16; o > 0; o >>= 1)
                acc[t][e] += __shfl_xor_sync(0xffffffffu, acc[t][e], o);

    if (lane == 0) {
        float esum[EDIM];
#pragma unroll
        for (int e = 0; e < EDIM; e++) esum[e] = 0.f;
#pragma unroll 1
        for (int t = 0; t < 4; t++) {
            float* a = acc[t];
            float mx = a[0]; int bi = 0;
#pragma unroll
            for (int e = 1; e < EDIM; e++) if (a[e] > mx) { mx = a[e]; bi = e; }
            float g[EDIM], sum = 0.f;
#pragma unroll
            for (int e = 0; e < EDIM; e++) { g[e] = expf(a[e] - mx); sum += g[e]; }
            float inv = 1.f / sum;
#pragma unroll
            for (int e = 0; e < EDIM; e++) { g[e] *= inv; esum[e] += g[e]; }
            g_exp[ta + t]  = bi;
            g_gate[ta + t] = g[bi];
            atomicAdd(&scnt[bi], 1);
        }
#pragma unroll
        for (int e = 0; e < EDIM; e++) atomicAdd(&ssum[e], esum[e]);
    }
    __syncthreads();
    if (tid < EDIM) {
        g_bsum[blockIdx.x * EDIM + tid] = ssum[tid];
        g_bcnt[blockIdx.x * EDIM + tid] = scnt[tid];
    }
}

// ======================= scatter: fused prefix + rank + copy ===============
// grid = 256 blocks x 32 tokens. Warp e computes base[e] = sum of counts in
// chunks < b; block 0 additionally reduces totals -> g_count + l_aux.
__global__ __launch_bounds__(256) void scatter_kernel(const float* __restrict__ x,
                                                      float* __restrict__ out, int out_size) {
    __shared__ int sbase[EDIM];
    __shared__ int se[32], sloc[32];
    __shared__ float s_sum[EDIM];
    __shared__ int   s_cnt[EDIM];
    int tid = threadIdx.x;
    int b = blockIdx.x;
    int warp = tid >> 5, lane = tid & 31;

    // warp e: exclusive chunk prefix for this block (chunks < b)
    {
        int e = warp;
        int s = 0;
        for (int c = lane; c < b; c += 32) s += g_bcnt[c * EDIM + e];
#pragma unroll
        for (int o = 16; o > 0; o >>= 1) s += __shfl_xor_sync(0xffffffffu, s, o);
        if (lane == 0) sbase[e] = s;
        if (b == 0) {   // block 0: full totals for g_count + l_aux
            int ct = 0; float sm = 0.f;
#pragma unroll
            for (int j = 0; j < 8; j++) {
                int c = lane * 8 + j;
                ct += g_bcnt[c * EDIM + e];
                sm += g_bsum[c * EDIM + e];
            }
#pragma unroll
            for (int o = 16; o > 0; o >>= 1) {
                ct += __shfl_xor_sync(0xffffffffu, ct, o);
                sm += __shfl_xor_sync(0xffffffffu, sm, o);
            }
            if (lane == 0) {
                g_count[e] = (ct < CAP) ? ct : CAP;
                s_cnt[e] = ct;
                s_sum[e] = sm;
            }
        }
    }
    __syncthreads();

    if (tid < 32) {
        int t = b * 32 + tid;
        int e = g_exp[t];
        unsigned mask = __match_any_sync(0xffffffffu, e);
        int rank = __popc(mask & ((1u << tid) - 1u));
        int loc = sbase[e] + rank;
        bool kept = loc < CAP;
        se[tid] = e;
        sloc[tid] = kept ? loc : -1;
        if (kept) g_slot2tok[e * CAP + loc] = t;
    }
    __syncthreads();

#pragma unroll 1
    for (int j = 0; j < 4; j++) {
        int tt = warp * 4 + j;
        int t = b * 32 + tt;
        int loc = sloc[tt];
        if (loc >= 0) {
            const float4* src = (const float4*)(x + (size_t)t * MDIM);
            __half2* row = (__half2*)(g_disp + ((size_t)se[tt] * CAP + loc) * MDIM);
#pragma unroll
            for (int k = 0; k < 8; k++) {
                float4 v = src[lane + k * 32];
                row[(lane + k * 32) * 2]     = __floats2half2_rn(v.x, v.y);
                row[(lane + k * 32) * 2 + 1] = __floats2half2_rn(v.z, v.w);
            }
        } else {
            float4* orow = (float4*)(out + (size_t)t * MDIM);
#pragma unroll
            for (int k = 0; k < 8; k++) orow[lane + k * 32] = make_float4(0.f, 0.f, 0.f, 0.f);
        }
    }
    if (b == 0 && tid == 0 && out_size > S_TOK * MDIM) {
        float l = 0.f;
#pragma unroll
        for (int e = 0; e < EDIM; e++)
            l += (s_sum[e] / (float)S_TOK) * ((float)s_cnt[e] / (float)S_TOK);
        out[(size_t)S_TOK * MDIM] = l * (float)EDIM;
    }
}

// ======================= fp16 mma GEMM, 3-stage pipeline ===================
static constexpr int GSMEM_BYTES = 3 * 32768 + 1024;

template <int K, int N, int EPI>
__global__ __launch_bounds__(256, 2) void mma_gemm(const __half* __restrict__ A,
                                                   const __half* __restrict__ B,
                                                   void* __restrict__ Cv,
                                                   int ytile0) {
    extern __shared__ char dynsmem[];
    char* sptr = (char*)((((uintptr_t)dynsmem) + 1023) & ~(uintptr_t)1023);
    uint32_t sbase = smem_u32(sptr);

    int tid = threadIdx.x;
    int wid = tid >> 5, lane = tid & 31;
    int row0 = (blockIdx.y + ytile0) * 128, col0 = blockIdx.x * 128;
    const __half* __restrict__ Be = B + (size_t)(row0 >> 10) * ((size_t)N * K);

    int lm = tid >> 1;
    int lh = tid & 1;
    const char* Ab = (const char*)(A + (size_t)(row0 + lm) * K);
    const char* Bb = (const char*)(Be + (size_t)(col0 + lm) * K);
    uint32_t swz = (uint32_t)(lm & 7);
    uint32_t dA = sbase + (uint32_t)lm * 128u;
    uint32_t dB = sbase + 16384u + (uint32_t)lm * 128u;

    auto load_tile = [&](int kt, int buf) {
        const char* As = Ab + kt * 128;
        const char* Bs = Bb + kt * 128;
        uint32_t off = (uint32_t)buf * 32768u;
#pragma unroll
        for (int c8 = 0; c8 < 4; c8++) {
            uint32_t lc = (uint32_t)(lh * 4 + c8);
            uint32_t p = (lc ^ swz) << 4;
            cp_async16(dA + off + p, As + lc * 16);
            cp_async16(dB + off + p, Bs + lc * 16);
        }
        CP_COMMIT();
    };

    int wm = (wid & 1) * 64;
    int wn = (wid >> 1) * 32;

    float acc[4][4][4];
#pragma unroll
    for (int i = 0; i < 4; i++)
#pragma unroll
        for (int j = 0; j < 4; j++)
#pragma unroll
            for (int q = 0; q < 4; q++) acc[i][j][q] = 0.f;

    constexpr int KT = K / 64;
    load_tile(0, 0);
    load_tile(1, 1);

    int rdbuf = 0, wrbuf = 2;
#pragma unroll 1
    for (int kt = 0; kt < KT; kt++) {
        if (kt + 2 < KT) { CP_WAIT(1); } else { CP_WAIT(0); }
        __syncthreads();
        if (kt + 2 < KT) load_tile(kt + 2, wrbuf);

        uint32_t sA = sbase + (uint32_t)rdbuf * 32768u;
        uint32_t sB = sA + 16384u;
#pragma unroll
        for (int kh = 0; kh < 2; kh++) {
            uint32_t bf[4][4];
#pragma unroll
            for (int jt = 0; jt < 4; jt++) {
                uint32_t row = (uint32_t)(wn + jt * 8 + (lane & 7));
                uint32_t c = (uint32_t)(lane >> 3) + (uint32_t)kh * 4u;
                ldmatrix_x4(bf[jt], sB + row * 128u + ((c ^ (row & 7u)) << 4));
            }
#pragma unroll
            for (int mi = 0; mi < 4; mi++) {
                uint32_t row = (uint32_t)(wm + mi * 16 + (lane & 15));
                uint32_t rbase = sA + row * 128u;
                uint32_t rsw = row & 7u;
#pragma unroll
                for (int s = 0; s < 2; s++) {
                    uint32_t c = (uint32_t)(kh * 4 + 2 * s + (lane >> 4));
                    uint32_t af[4];
                    ldmatrix_x4(af, rbase + ((c ^ rsw) << 4));
#pragma unroll
                    for (int jt = 0; jt < 4; jt++)
                        mma_fp16(acc[mi][jt], af, bf[jt][2 * s], bf[jt][2 * s + 1]);
                }
            }
        }
        rdbuf = (rdbuf == 2) ? 0 : rdbuf + 1;
        wrbuf = (wrbuf == 2) ? 0 : wrbuf + 1;
    }
    __syncthreads();

    if (EPI == 0) {
        __half* sh = (__half*)sptr;     // [128][132]
#pragma unroll
        for (int mi = 0; mi < 4; mi++) {
            int rl = wm + mi * 16 + (lane >> 2);
#pragma unroll
            for (int jt = 0; jt < 4; jt++) {
                int c = wn + jt * 8 + (lane & 3) * 2;
                *(__half2*)(sh + rl * 132 + c) =
                    __floats2half2_rn(fmaxf(acc[mi][jt][0], 0.f), fmaxf(acc[mi][jt][1], 0.f));
                *(__half2*)(sh + (rl + 8) * 132 + c) =
                    __floats2half2_rn(fmaxf(acc[mi][jt][2], 0.f), fmaxf(acc[mi][jt][3], 0.f));
            }
        }
        __syncthreads();
        __half* C = (__half*)Cv;
#pragma unroll
        for (int i = 0; i < 16; i++) {
            int rl = wid * 16 + i;
            uint2 v = *(uint2*)(sh + rl * 132 + lane * 4);
            *(uint2*)(C + (size_t)(row0 + rl) * N + col0 + lane * 4) = v;
        }
    } else {
        float* sf = (float*)sptr;       // [128][132]
#pragma unroll
        for (int mi = 0; mi < 4; mi++) {
            int rl = wm + mi * 16 + (lane >> 2);
#pragma unroll
            for (int jt = 0; jt < 4; jt++) {
                int c = wn + jt * 8 + (lane & 3) * 2;
                *(float2*)(sf + rl * 132 + c) = make_float2(acc[mi][jt][0], acc[mi][jt][1]);
                *(float2*)(sf + (rl + 8) * 132 + c) = make_float2(acc[mi][jt][2], acc[mi][jt][3]);
            }
        }
        __syncthreads();
        float* out = (float*)Cv;
#pragma unroll 1
        for (int i = 0; i < 16; i++) {
            int rl = wid * 16 + i;
            int slot = row0 + rl;
            int e = slot >> 10, loc = slot & (CAP - 1);
            if (loc < g_count[e]) {
                int tok = g_slot2tok[slot];
                float g = g_gate[tok];
                float4 v = *(float4*)(sf + rl * 132 + lane * 4);
                v.x *= g; v.y *= g; v.z *= g; v.w *= g;
                *(float4*)(out + (size_t)tok * MDIM + col0 + lane * 4) = v;
            }
        }
    }
}

// ======================= launch (R11 schedule) =============================
extern "C" void kernel_launch(void* const* d_in, const int* in_sizes, int n_in,
                              void* d_out, int out_size) {
    const float* x  = (const float*)d_in[0];
    const float* wg = (const float*)d_in[1];
    const float* w1 = (const float*)d_in[2];
    const float* w2 = (const float*)d_in[3];
    float* out = (float*)d_out;

    __half *p_disp, *p_h, *p_w1t, *p_w2t;
    cudaGetSymbolAddress((void**)&p_disp, g_disp);
    cudaGetSymbolAddress((void**)&p_h,    g_h);
    cudaGetSymbolAddress((void**)&p_w1t,  g_w1t);
    cudaGetSymbolAddress((void**)&p_w2t,  g_w2t);

    static cudaStream_t sW = nullptr, sA = nullptr, sB = nullptr;
    static cudaEvent_t evStart, evW1, evW2, evDisp, ev1a, ev1b, ev2a, ev2b;
    static bool init_done = false;
    if (!init_done) {
        cudaFuncSetAttribute(mma_gemm<MDIM, HDIM, 0>,
                             cudaFuncAttributeMaxDynamicSharedMemorySize, GSMEM_BYTES);
        cudaFuncSetAttribute(mma_gemm<HDIM, MDIM, 1>,
                             cudaFuncAttributeMaxDynamicSharedMemorySize, GSMEM_BYTES);
        cudaStreamCreateWithFlags(&sW, cudaStreamNonBlocking);
        cudaStreamCreateWithFlags(&sA, cudaStreamNonBlocking);
        cudaStreamCreateWithFlags(&sB, cudaStreamNonBlocking);
        cudaEventCreateWithFlags(&evStart, cudaEventDisableTiming);
        cudaEventCreateWithFlags(&evW1, cudaEventDisableTiming);
        cudaEventCreateWithFlags(&evW2, cudaEventDisableTiming);
        cudaEventCreateWithFlags(&evDisp, cudaEventDisableTiming);
        cudaEventCreateWithFlags(&ev1a, cudaEventDisableTiming);
        cudaEventCreateWithFlags(&ev1b, cudaEventDisableTiming);
        cudaEventCreateWithFlags(&ev2a, cudaEventDisableTiming);
        cudaEventCreateWithFlags(&ev2b, cudaEventDisableTiming);
        init_done = true;
    }

    // fork weight conversion
    cudaEventRecord(evStart, 0);
    cudaStreamWaitEvent(sW, evStart, 0);
    wconv_kernel<MDIM, HDIM><<<dim3(HDIM / 32, MDIM / 64, EDIM), 256, 0, sW>>>(w1, p_w1t);
    cudaEventRecord(evW1, sW);
    wconv_kernel<HDIM, MDIM><<<dim3(MDIM / 32, HDIM / 64, EDIM), 256, 0, sW>>>(w2, p_w2t);
    cudaEventRecord(evW2, sW);

    // token pipeline on main stream: gate -> scatter (scan fused into scatter)
    gate_kernel<<<S_TOK / 32, 256>>>(x, wg);
    scatter_kernel<<<S_TOK / 32, 256>>>(x, out, out_size);
    cudaEventRecord(evDisp, 0);

    // expert-half chunked GEMMs (R11-proven)
    cudaStreamWaitEvent(sA, evDisp, 0);
    cudaStreamWaitEvent(sA, evW1, 0);
    mma_gemm<MDIM, HDIM, 0><<<dim3(HDIM / 128, 32), 256, GSMEM_BYTES, sA>>>(p_disp, p_w1t, p_h, 0);
    cudaEventRecord(ev1a, sA);

    cudaStreamWaitEvent(sB, evDisp, 0);
    cudaStreamWaitEvent(sB, evW1, 0);
    mma_gemm<MDIM, HDIM, 0><<<dim3(HDIM / 128, 32), 256, GSMEM_BYTES, sB>>>(p_disp, p_w1t, p_h, 32);
    cudaEventRecord(ev1b, sB);

    cudaStreamWaitEvent(sA, evW2, 0);
    mma_gemm<HDIM, MDIM, 1><<<dim3(MDIM / 128, 32), 256, GSMEM_BYTES, sA>>>(p_h, p_w2t, out, 0);
    cudaEventRecord(ev2a, sA);

    cudaStreamWaitEvent(sB, evW2, 0);
    mma_gemm<HDIM, MDIM, 1><<<dim3(MDIM / 128, 32), 256, GSMEM_BYTES, sB>>>(p_h, p_w2t, out, 32);
    cudaEventRecord(ev2b, sB);

    cudaStreamWaitEvent(0, ev2a, 0);
    cudaStreamWaitEvent(0, ev2b, 0);
}

// round 17
// speedup vs baseline: 1.0952x; 1.0058x over previous
#include <cuda_runtime.h>
#include <cuda_fp16.h>
#include <cstdint>

#define S_TOK 8192
#define MDIM  1024
#define EDIM  8
#define HDIM  4096
#define CAP   1024

// ======================= helpers ===========================================
__device__ __forceinline__ uint32_t smem_u32(const void* p) {
    uint32_t a;
    asm("{ .reg .u64 t; cvta.to.shared.u64 t, %1; cvt.u32.u64 %0, t; }" : "=r"(a) : "l"(p));
    return a;
}
__device__ __forceinline__ void cp_async16(uint32_t dst, const void* src) {
    asm volatile("cp.async.cg.shared.global [%0], [%1], 16;" :: "r"(dst), "l"(src));
}
// predicated: src-size 0 -> zero-fill destination (no gmem read)
__device__ __forceinline__ void cp_async16p(uint32_t dst, const void* src, int sz) {
    asm volatile("cp.async.cg.shared.global [%0], [%1], 16, %2;" :: "r"(dst), "l"(src), "r"(sz));
}
#define CP_COMMIT() asm volatile("cp.async.commit_group;" ::: "memory")
#define CP_WAIT(n)  asm volatile("cp.async.wait_group %0;" :: "n"(n) : "memory")

__device__ __forceinline__ void ldmatrix_x4(uint32_t* r, uint32_t addr) {
    asm volatile("ldmatrix.sync.aligned.m8n8.x4.shared.b16 {%0,%1,%2,%3}, [%4];"
                 : "=r"(r[0]), "=r"(r[1]), "=r"(r[2]), "=r"(r[3]) : "r"(addr));
}
__device__ __forceinline__ void mma_fp16(float* c, const uint32_t* a, uint32_t b0, uint32_t b1) {
    asm volatile("mma.sync.aligned.m16n8k16.row.col.f32.f16.f16.f32 "
                 "{%0,%1,%2,%3}, {%4,%5,%6,%7}, {%8,%9}, {%0,%1,%2,%3};"
                 : "+f"(c[0]), "+f"(c[1]), "+f"(c[2]), "+f"(c[3])
                 : "r"(a[0]), "r"(a[1]), "r"(a[2]), "r"(a[3]), "r"(b0), "r"(b1));
}

// ======================= scratch ===========================================
__device__ float g_gate[S_TOK];
__device__ int   g_exp[S_TOK];
__device__ int   g_slot2tok[S_TOK];      // zero-init; kept slots rewritten each run
__device__ float g_bsum[256 * EDIM];
__device__ int   g_bcnt[256 * EDIM];
__device__ int   g_count[EDIM];
__device__ __half g_xh[(size_t)S_TOK * MDIM];   // token-ordered fp16 x (16MB)
__device__ __half g_h[(size_t)S_TOK * HDIM];
__device__ __half g_w1t[(size_t)EDIM * HDIM * MDIM];
__device__ __half g_w2t[(size_t)EDIM * MDIM * HDIM];

// ======================= weight transpose + fp16 convert ===================
template <int K, int N>
__global__ __launch_bounds__(256) void wconv_kernel(const float* __restrict__ W,
                                                    __half* __restrict__ Wt) {
    __shared__ float tile[64][33];
    int e = blockIdx.z;
    const float* We = W + (size_t)e * K * N;
    __half* Wte = Wt + (size_t)e * N * K;
    int n0 = blockIdx.x * 32, k0 = blockIdx.y * 64;
    int tid = threadIdx.x;
#pragma unroll
    for (int i = tid; i < 64 * 32; i += 256) {
        int k = i >> 5, n = i & 31;
        tile[k][n] = We[(size_t)(k0 + k) * N + n0 + n];
    }
    __syncthreads();
#pragma unroll
    for (int i = tid; i < 32 * 32; i += 256) {
        int n = i >> 5, kp = i & 31;
        __half2 h = __floats2half2_rn(tile[2 * kp][n], tile[2 * kp + 1][n]);
        *(__half2*)(Wte + (size_t)(n0 + n) * K + k0 + 2 * kp) = h;
    }
}

// ======================= gating: 4 tokens/warp + fp16 x + chunk counts =====
__global__ __launch_bounds__(256) void gate_kernel(const float* __restrict__ x,
                                                   const float* __restrict__ wg) {
    __shared__ float swg[EDIM][MDIM];
    __shared__ float ssum[EDIM];
    __shared__ int   scnt[EDIM];
    int tid = threadIdx.x;
    for (int i = tid; i < MDIM * EDIM; i += 256)
        swg[i & 7][i >> 3] = wg[i];
    if (tid < EDIM) { ssum[tid] = 0.f; scnt[tid] = 0; }
    __syncthreads();

    int warp = tid >> 5, lane = tid & 31;
    int ta = blockIdx.x * 32 + warp * 4;
    const float4* xr0 = (const float4*)(x + (size_t)ta * MDIM);
    const float4* xr1 = (const float4*)(x + (size_t)(ta + 1) * MDIM);
    const float4* xr2 = (const float4*)(x + (size_t)(ta + 2) * MDIM);
    const float4* xr3 = (const float4*)(x + (size_t)(ta + 3) * MDIM);
    __half2* xh0 = (__half2*)(g_xh + (size_t)ta * MDIM);
    __half2* xh1 = (__half2*)(g_xh + (size_t)(ta + 1) * MDIM);
    __half2* xh2 = (__half2*)(g_xh + (size_t)(ta + 2) * MDIM);
    __half2* xh3 = (__half2*)(g_xh + (size_t)(ta + 3) * MDIM);

    float acc[4][EDIM];
#pragma unroll
    for (int t = 0; t < 4; t++)
#pragma unroll
        for (int e = 0; e < EDIM; e++) acc[t][e] = 0.f;

#pragma unroll 1
    for (int m4 = lane; m4 < MDIM / 4; m4 += 32) {
        float4 v0 = xr0[m4];
        float4 v1 = xr1[m4];
        float4 v2 = xr2[m4];
        float4 v3 = xr3[m4];
        xh0[m4 * 2] = __floats2half2_rn(v0.x, v0.y);
        xh0[m4 * 2 + 1] = __floats2half2_rn(v0.z, v0.w);
        xh1[m4 * 2] = __floats2half2_rn(v1.x, v1.y);
        xh1[m4 * 2 + 1] = __floats2half2_rn(v1.z, v1.w);
        xh2[m4 * 2] = __floats2half2_rn(v2.x, v2.y);
        xh2[m4 * 2 + 1] = __floats2half2_rn(v2.z, v2.w);
        xh3[m4 * 2] = __floats2half2_rn(v3.x, v3.y);
        xh3[m4 * 2 + 1] = __floats2half2_rn(v3.z, v3.w);
#pragma unroll
        for (int e = 0; e < EDIM; e++) {
            float4 w = ((const float4*)swg[e])[m4];
            acc[0][e] = fmaf(v0.x, w.x, fmaf(v0.y, w.y, fmaf(v0.z, w.z, fmaf(v0.w, w.w, acc[0][e]))));
            acc[1][e] = fmaf(v1.x, w.x, fmaf(v1.y, w.y, fmaf(v1.z, w.z, fmaf(v1.w, w.w, acc[1][e]))));
            acc[2][e] = fmaf(v2.x, w.x, fmaf(v2.y, w.y, fmaf(v2.z, w.z, fmaf(v2.w, w.w, acc[2][e]))));
            acc[3][e] = fmaf(v3.x, w.x, fmaf(v3.y, w.y, fmaf(v3.z, w.z, fmaf(v3.w, w.w, acc[3][e]))));
        }
    }
#pragma unroll
    for (int t = 0; t < 4; t++)
#pragma unroll
        for (int e = 0; e < EDIM; e++)
#pragma unroll
            for (int o = 16; o > 0; o >>= 1)
                acc[t][e] += __shfl_xor_sync(0xffffffffu, acc[t][e], o);

    if (lane == 0) {
        float esum[EDIM];
#pragma unroll
        for (int e = 0; e < EDIM; e++) esum[e] = 0.f;
#pragma unroll 1
        for (int t = 0; t < 4; t++) {
            float* a = acc[t];
            float mx = a[0]; int bi = 0;
#pragma unroll
            for (int e = 1; e < EDIM; e++) if (a[e] > mx) { mx = a[e]; bi = e; }
            float g[EDIM], sum = 0.f;
#pragma unroll
            for (int e = 0; e < EDIM; e++) { g[e] = expf(a[e] - mx); sum += g[e]; }
            float inv = 1.f / sum;
#pragma unroll
            for (int e = 0; e < EDIM; e++) { g[e] *= inv; esum[e] += g[e]; }
            g_exp[ta + t]  = bi;
            g_gate[ta + t] = g[bi];
            atomicAdd(&scnt[bi], 1);
        }
#pragma unroll
        for (int e = 0; e < EDIM; e++) atomicAdd(&ssum[e], esum[e]);
    }
    __syncthreads();
    if (tid < EDIM) {
        g_bsum[blockIdx.x * EDIM + tid] = ssum[tid];
        g_bcnt[blockIdx.x * EDIM + tid] = scnt[tid];
    }
}

// ======================= scatter: metadata only ============================
// grid = 256 x 32 tokens: prefix + rank -> slot2tok; dropped rows -> zero out
__global__ __launch_bounds__(256) void scatter_kernel(float* __restrict__ out, int out_size) {
    __shared__ int sbase[EDIM];
    __shared__ int sloc[32];
    __shared__ float s_sum[EDIM];
    __shared__ int   s_cnt[EDIM];
    int tid = threadIdx.x;
    int b = blockIdx.x;
    int warp = tid >> 5, lane = tid & 31;

    {
        int e = warp;
        int s = 0;
        for (int c = lane; c < b; c += 32) s += g_bcnt[c * EDIM + e];
#pragma unroll
        for (int o = 16; o > 0; o >>= 1) s += __shfl_xor_sync(0xffffffffu, s, o);
        if (lane == 0) sbase[e] = s;
        if (b == 0) {
            int ct = 0; float sm = 0.f;
#pragma unroll
            for (int j = 0; j < 8; j++) {
                int c = lane * 8 + j;
                ct += g_bcnt[c * EDIM + e];
                sm += g_bsum[c * EDIM + e];
            }
#pragma unroll
            for (int o = 16; o > 0; o >>= 1) {
                ct += __shfl_xor_sync(0xffffffffu, ct, o);
                sm += __shfl_xor_sync(0xffffffffu, sm, o);
            }
            if (lane == 0) {
                g_count[e] = (ct < CAP) ? ct : CAP;
                s_cnt[e] = ct;
                s_sum[e] = sm;
            }
        }
    }
    __syncthreads();

    if (tid < 32) {
        int t = b * 32 + tid;
        int e = g_exp[t];
        unsigned mask = __match_any_sync(0xffffffffu, e);
        int rank = __popc(mask & ((1u << tid) - 1u));
        int loc = sbase[e] + rank;
        bool kept = loc < CAP;
        sloc[tid] = kept ? loc : -1;
        if (kept) g_slot2tok[e * CAP + loc] = t;
    }
    __syncthreads();

    // zero-fill out rows of dropped tokens (rare)
#pragma unroll 1
    for (int j = 0; j < 4; j++) {
        int tt = warp * 4 + j;
        if (sloc[tt] < 0) {
            int t = b * 32 + tt;
            float4* orow = (float4*)(out + (size_t)t * MDIM);
#pragma unroll
            for (int k = 0; k < 8; k++) orow[lane + k * 32] = make_float4(0.f, 0.f, 0.f, 0.f);
        }
    }
    if (b == 0 && tid == 0 && out_size > S_TOK * MDIM) {
        float l = 0.f;
#pragma unroll
        for (int e = 0; e < EDIM; e++)
            l += (s_sum[e] / (float)S_TOK) * ((float)s_cnt[e] / (float)S_TOK);
        out[(size_t)S_TOK * MDIM] = l * (float)EDIM;
    }
}

// ======================= fp16 mma GEMM, 3-stage pipeline ===================
// EPI 0 (GEMM1): A gathered indirectly via slot2tok from g_xh; relu -> g_h
// EPI 1 (GEMM2): A direct from g_h; combine -> out
static constexpr int GSMEM_BYTES = 3 * 32768 + 1024;

template <int K, int N, int EPI>
__global__ __launch_bounds__(256, 2) void mma_gemm(const __half* __restrict__ A,
                                                   const __half* __restrict__ B,
                                                   void* __restrict__ Cv,
                                                   int ytile0) {
    extern __shared__ char dynsmem[];
    char* sptr = (char*)((((uintptr_t)dynsmem) + 1023) & ~(uintptr_t)1023);
    uint32_t sbase = smem_u32(sptr);

    int tid = threadIdx.x;
    int wid = tid >> 5, lane = tid & 31;
    int row0 = (blockIdx.y + ytile0) * 128, col0 = blockIdx.x * 128;
    const __half* __restrict__ Be = B + (size_t)(row0 >> 10) * ((size_t)N * K);

    int lm = tid >> 1;
    int lh = tid & 1;
    const char* Ab;
    int aSz = 16;
    if (EPI == 0) {
        int slot = row0 + lm;
        int e = slot >> 10, loc = slot & (CAP - 1);
        bool valid = loc < g_count[e];
        int tok = g_slot2tok[slot] & (S_TOK - 1);
        aSz = valid ? 16 : 0;
        Ab = (const char*)(A + (size_t)tok * K);
    } else {
        Ab = (const char*)(A + (size_t)(row0 + lm) * K);
    }
    const char* Bb = (const char*)(Be + (size_t)(col0 + lm) * K);
    uint32_t swz = (uint32_t)(lm & 7);
    uint32_t dA = sbase + (uint32_t)lm * 128u;
    uint32_t dB = sbase + 16384u + (uint32_t)lm * 128u;

    auto load_tile = [&](int kt, int buf) {
        const char* As = Ab + kt * 128;
        const char* Bs = Bb + kt * 128;
        uint32_t off = (uint32_t)buf * 32768u;
#pragma unroll
        for (int c8 = 0; c8 < 4; c8++) {
            uint32_t lc = (uint32_t)(lh * 4 + c8);
            uint32_t p = (lc ^ swz) << 4;
            if (EPI == 0) cp_async16p(dA + off + p, As + lc * 16, aSz);
            else          cp_async16(dA + off + p, As + lc * 16);
            cp_async16(dB + off + p, Bs + lc * 16);
        }
        CP_COMMIT();
    };

    int wm = (wid & 1) * 64;
    int wn = (wid >> 1) * 32;

    float acc[4][4][4];
#pragma unroll
    for (int i = 0; i < 4; i++)
#pragma unroll
        for (int j = 0; j < 4; j++)
#pragma unroll
            for (int q = 0; q < 4; q++) acc[i][j][q] = 0.f;

    constexpr int KT = K / 64;
    load_tile(0, 0);
    load_tile(1, 1);

    int rdbuf = 0, wrbuf = 2;
#pragma unroll 1
    for (int kt = 0; kt < KT; kt++) {
        if (kt + 2 < KT) { CP_WAIT(1); } else { CP_WAIT(0); }
        __syncthreads();
        if (kt + 2 < KT) load_tile(kt + 2, wrbuf);

        uint32_t sA = sbase + (uint32_t)rdbuf * 32768u;
        uint32_t sB = sA + 16384u;
#pragma unroll
        for (int kh = 0; kh < 2; kh++) {
            uint32_t bf[4][4];
#pragma unroll
            for (int jt = 0; jt < 4; jt++) {
                uint32_t row = (uint32_t)(wn + jt * 8 + (lane & 7));
                uint32_t c = (uint32_t)(lane >> 3) + (uint32_t)kh * 4u;
                ldmatrix_x4(bf[jt], sB + row * 128u + ((c ^ (row & 7u)) << 4));
            }
#pragma unroll
            for (int mi = 0; mi < 4; mi++) {
                uint32_t row = (uint32_t)(wm + mi * 16 + (lane & 15));
                uint32_t rbase = sA + row * 128u;
                uint32_t rsw = row & 7u;
#pragma unroll
                for (int s = 0; s < 2; s++) {
                    uint32_t c = (uint32_t)(kh * 4 + 2 * s + (lane >> 4));
                    uint32_t af[4];
                    ldmatrix_x4(af, rbase + ((c ^ rsw) << 4));
#pragma unroll
                    for (int jt = 0; jt < 4; jt++)
                        mma_fp16(acc[mi][jt], af, bf[jt][2 * s], bf[jt][2 * s + 1]);
                }
            }
        }
        rdbuf = (rdbuf == 2) ? 0 : rdbuf + 1;
        wrbuf = (wrbuf == 2) ? 0 : wrbuf + 1;
    }
    __syncthreads();

    if (EPI == 0) {
        __half* sh = (__half*)sptr;     // [128][132]
#pragma unroll
        for (int mi = 0; mi < 4; mi++) {
            int rl = wm + mi * 16 + (lane >> 2);
#pragma unroll
            for (int jt = 0; jt < 4; jt++) {
                int c = wn + jt * 8 + (lane & 3) * 2;
                *(__half2*)(sh + rl * 132 + c) =
                    __floats2half2_rn(fmaxf(acc[mi][jt][0], 0.f), fmaxf(acc[mi][jt][1], 0.f));
                *(__half2*)(sh + (rl + 8) * 132 + c) =
                    __floats2half2_rn(fmaxf(acc[mi][jt][2], 0.f), fmaxf(acc[mi][jt][3], 0.f));
            }
        }
        __syncthreads();
        __half* C = (__half*)Cv;
#pragma unroll
        for (int i = 0; i < 16; i++) {
            int rl = wid * 16 + i;
            uint2 v = *(uint2*)(sh + rl * 132 + lane * 4);
            *(uint2*)(C + (size_t)(row0 + rl) * N + col0 + lane * 4) = v;
        }
    } else {
        float* sf = (float*)sptr;       // [128][132]
#pragma unroll
        for (int mi = 0; mi < 4; mi++) {
            int rl = wm + mi * 16 + (lane >> 2);
#pragma unroll
            for (int jt = 0; jt < 4; jt++) {
                int c = wn + jt * 8 + (lane & 3) * 2;
                *(float2*)(sf + rl * 132 + c) = make_float2(acc[mi][jt][0], acc[mi][jt][1]);
                *(float2*)(sf + (rl + 8) * 132 + c) = make_float2(acc[mi][jt][2], acc[mi][jt][3]);
            }
        }
        __syncthreads();
        float* out = (float*)Cv;
#pragma unroll 1
        for (int i = 0; i < 16; i++) {
            int rl = wid * 16 + i;
            int slot = row0 + rl;
            int e = slot >> 10, loc = slot & (CAP - 1);
            if (loc < g_count[e]) {
                int tok = g_slot2tok[slot];
                float g = g_gate[tok];
                float4 v = *(float4*)(sf + rl * 132 + lane * 4);
                v.x *= g; v.y *= g; v.z *= g; v.w *= g;
                *(float4*)(out + (size_t)tok * MDIM + col0 + lane * 4) = v;
            }
        }
    }
}

// ======================= launch (R11 schedule) =============================
extern "C" void kernel_launch(void* const* d_in, const int* in_sizes, int n_in,
                              void* d_out, int out_size) {
    const float* x  = (const float*)d_in[0];
    const float* wg = (const float*)d_in[1];
    const float* w1 = (const float*)d_in[2];
    const float* w2 = (const float*)d_in[3];
    float* out = (float*)d_out;

    __half *p_xh, *p_h, *p_w1t, *p_w2t;
    cudaGetSymbolAddress((void**)&p_xh,  g_xh);
    cudaGetSymbolAddress((void**)&p_h,   g_h);
    cudaGetSymbolAddress((void**)&p_w1t, g_w1t);
    cudaGetSymbolAddress((void**)&p_w2t, g_w2t);

    static cudaStream_t sW = nullptr, sA = nullptr, sB = nullptr;
    static cudaEvent_t evStart, evW1, evW2, evDisp, ev1a, ev1b, ev2a, ev2b;
    static bool init_done = false;
    if (!init_done) {
        cudaFuncSetAttribute(mma_gemm<MDIM, HDIM, 0>,
                             cudaFuncAttributeMaxDynamicSharedMemorySize, GSMEM_BYTES);
        cudaFuncSetAttribute(mma_gemm<HDIM, MDIM, 1>,
                             cudaFuncAttributeMaxDynamicSharedMemorySize, GSMEM_BYTES);
        cudaStreamCreateWithFlags(&sW, cudaStreamNonBlocking);
        cudaStreamCreateWithFlags(&sA, cudaStreamNonBlocking);
        cudaStreamCreateWithFlags(&sB, cudaStreamNonBlocking);
        cudaEventCreateWithFlags(&evStart, cudaEventDisableTiming);
        cudaEventCreateWithFlags(&evW1, cudaEventDisableTiming);
        cudaEventCreateWithFlags(&evW2, cudaEventDisableTiming);
        cudaEventCreateWithFlags(&evDisp, cudaEventDisableTiming);
        cudaEventCreateWithFlags(&ev1a, cudaEventDisableTiming);
        cudaEventCreateWithFlags(&ev1b, cudaEventDisableTiming);
        cudaEventCreateWithFlags(&ev2a, cudaEventDisableTiming);
        cudaEventCreateWithFlags(&ev2b, cudaEventDisableTiming);
        init_done = true;
    }

    // fork weight conversion
    cudaEventRecord(evStart, 0);
    cudaStreamWaitEvent(sW, evStart, 0);
    wconv_kernel<MDIM, HDIM><<<dim3(HDIM / 32, MDIM / 64, EDIM), 256, 0, sW>>>(w1, p_w1t);
    cudaEventRecord(evW1, sW);
    wconv_kernel<HDIM, MDIM><<<dim3(MDIM / 32, HDIM / 64, EDIM), 256, 0, sW>>>(w2, p_w2t);
    cudaEventRecord(evW2, sW);

    // token pipeline: gate (writes fp16 x) -> scatter (metadata only)
    gate_kernel<<<S_TOK / 32, 256>>>(x, wg);
    scatter_kernel<<<S_TOK / 32, 256>>>(out, out_size);
    cudaEventRecord(evDisp, 0);

    // expert-half chunked GEMMs (R11-proven); GEMM1 gathers A via slot2tok
    cudaStreamWaitEvent(sA, evDisp, 0);
    cudaStreamWaitEvent(sA, evW1, 0);
    mma_gemm<MDIM, HDIM, 0><<<dim3(HDIM / 128, 32), 256, GSMEM_BYTES, sA>>>(p_xh, p_w1t, p_h, 0);
    cudaEventRecord(ev1a, sA);

    cudaStreamWaitEvent(sB, evDisp, 0);
    cudaStreamWaitEvent(sB, evW1, 0);
    mma_gemm<MDIM, HDIM, 0><<<dim3(HDIM / 128, 32), 256, GSMEM_BYTES, sB>>>(p_xh, p_w1t, p_h, 32);
    cudaEventRecord(ev1b, sB);

    cudaStreamWaitEvent(sA, evW2, 0);
    mma_gemm<HDIM, MDIM, 1><<<dim3(MDIM / 128, 32), 256, GSMEM_BYTES, sA>>>(p_h, p_w2t, out, 0);
    cudaEventRecord(ev2a, sA);

    cudaStreamWaitEvent(sB, evW2, 0);
    mma_gemm<HDIM, MDIM, 1><<<dim3(MDIM / 128, 32), 256, GSMEM_BYTES, sB>>>(p_h, p_w2t, out, 32);
    cudaEventRecord(ev2b, sB);

    cudaStreamWaitEvent(0, ev2a, 0);
    cudaStreamWaitEvent(0, ev2b, 0);
}